// round 2
// baseline (speedup 1.0000x reference)
#include <cuda_runtime.h>
#include <math.h>
#include <stdint.h>

// Problem constants
#define DIMK 4096
#define HQ   32
#define HKV  8
#define HD   128
#define REP  (HQ / HKV)
#define MAXS 4096
#define ATT_SCALE 0.08838834764831845f   // 1/sqrt(128)

// Scratch (device globals: allocation-free per harness rules)
__device__ float g_Q[(size_t)MAXS * HQ * HD];
__device__ float g_K[(size_t)MAXS * HKV * HD];
__device__ float g_V[(size_t)MAXS * HKV * HD];
__device__ float g_O[(size_t)MAXS * HQ * HD];

// ---------------------------------------------------------------------------
// GEMM: C[M,N] = A[M,K] @ B[N,K]^T      (all fp32, M%128==0, N%128==0, K%16==0)
// 128x128 tile, BK=16, 256 threads, 8x8 micro-tile per thread.
// ---------------------------------------------------------------------------
#define GBM 128
#define GBN 128
#define GBK 16

__global__ __launch_bounds__(256, 2)
void gemm_nt(const float* __restrict__ A, const float* __restrict__ B,
             float* __restrict__ C, int M, int N, int K) {
    __shared__ __align__(16) float As[GBK][GBM + 4];
    __shared__ __align__(16) float Bs[GBK][GBN + 4];

    const int tid = threadIdx.x;
    const int rx  = tid & 15;
    const int ry  = tid >> 4;
    const int m0  = ry * 8;
    const int n0  = rx * 8;
    const int bm  = blockIdx.y * GBM;
    const int bn  = blockIdx.x * GBN;

    float acc[8][8];
#pragma unroll
    for (int i = 0; i < 8; i++)
#pragma unroll
        for (int j = 0; j < 8; j++) acc[i][j] = 0.f;

    for (int kb = 0; kb < K; kb += GBK) {
        // Stage A and B tiles (transposed into [k][m] / [k][n])
#pragma unroll
        for (int t = 0; t < 2; t++) {
            int c  = tid + t * 256;        // 512 float4 chunks per tile
            int r  = c >> 2;               // row within tile (0..127)
            int kq = (c & 3) * 4;          // k sub-offset (0,4,8,12)
            float4 a4 = *(const float4*)(A + (size_t)(bm + r) * K + kb + kq);
            As[kq + 0][r] = a4.x;
            As[kq + 1][r] = a4.y;
            As[kq + 2][r] = a4.z;
            As[kq + 3][r] = a4.w;
            float4 b4 = *(const float4*)(B + (size_t)(bn + r) * K + kb + kq);
            Bs[kq + 0][r] = b4.x;
            Bs[kq + 1][r] = b4.y;
            Bs[kq + 2][r] = b4.z;
            Bs[kq + 3][r] = b4.w;
        }
        __syncthreads();

#pragma unroll
        for (int k = 0; k < GBK; k++) {
            float af[8], bf[8];
            *(float4*)&af[0] = *(const float4*)&As[k][m0];
            *(float4*)&af[4] = *(const float4*)&As[k][m0 + 4];
            *(float4*)&bf[0] = *(const float4*)&Bs[k][n0];
            *(float4*)&bf[4] = *(const float4*)&Bs[k][n0 + 4];
#pragma unroll
            for (int i = 0; i < 8; i++)
#pragma unroll
                for (int j = 0; j < 8; j++)
                    acc[i][j] = fmaf(af[i], bf[j], acc[i][j]);
        }
        __syncthreads();
    }

#pragma unroll
    for (int i = 0; i < 8; i++) {
        float* crow = C + (size_t)(bm + m0 + i) * N + bn + n0;
#pragma unroll
        for (int j = 0; j < 8; j += 4) {
            float4 o = make_float4(acc[i][j], acc[i][j + 1], acc[i][j + 2], acc[i][j + 3]);
            *(float4*)(crow + j) = o;
        }
    }
}

// ---------------------------------------------------------------------------
// RoPE (interleaved pairs), in-place on T[S, nh, 128]
// freqs_cis layout: [S, 64, 2] -> fc[s*128 + 2*i + {0:cos,1:sin}]
// ---------------------------------------------------------------------------
__global__ void rope_kernel(float* __restrict__ T, const float* __restrict__ fc,
                            int S, int nh) {
    int idx   = blockIdx.x * blockDim.x + threadIdx.x;
    int total = S * nh * (HD / 2);
    if (idx >= total) return;
    int i = idx & 63;
    int h = (idx >> 6) % nh;
    int s = idx / (64 * nh);
    float c  = fc[(size_t)s * HD + 2 * i];
    float sn = fc[(size_t)s * HD + 2 * i + 1];
    size_t base = ((size_t)s * nh + h) * HD + 2 * i;
    float t0 = T[base];
    float t1 = T[base + 1];
    T[base]     = t0 * c - t1 * sn;
    T[base + 1] = t0 * sn + t1 * c;
}

// ---------------------------------------------------------------------------
// Flash attention with segmented causal mask (GQA via head mapping).
// One block = (64-query tile, head). 128 threads. Online softmax.
// ---------------------------------------------------------------------------
#define QS_STR 129
#define KS_STR 129
#define VS_STR 132
#define SS_STR 65
// floats: Qs 64*129, Ks 64*129, Vs 64*132, Ss 64*65, m/l/alpha 3*64, seg 64 ints
#define ATTN_SMEM_BYTES ((64 * QS_STR + 64 * KS_STR + 64 * VS_STR + 64 * SS_STR + 3 * 64) * 4 + 64 * 4)

__global__ __launch_bounds__(128, 1)
void attn_kernel(const float* __restrict__ Q, const float* __restrict__ K,
                 const float* __restrict__ V, const int* __restrict__ seqlens,
                 int nseq, float* __restrict__ O, int S) {
    extern __shared__ __align__(16) float sm[];
    float* Qs    = sm;
    float* Ks    = Qs + 64 * QS_STR;
    float* Vs    = Ks + 64 * KS_STR;
    float* Ss    = Vs + 64 * VS_STR;
    float* row_m = Ss + 64 * SS_STR;
    float* row_l = row_m + 64;
    float* row_a = row_l + 64;
    int*   seg_s = (int*)(row_a + 64);

    const int tid = threadIdx.x;
    const int h   = blockIdx.y;
    const int kvh = h / REP;
    const int q0  = blockIdx.x * 64;

    // Load Q tile: 64 rows x 128 d (row-major, stride 129)
#pragma unroll
    for (int t = 0; t < 16; t++) {
        int c  = t * 128 + tid;
        int r  = c >> 5;
        int dq = (c & 31) * 4;
        float4 v = *(const float4*)(Q + ((size_t)(q0 + r) * HQ + h) * HD + dq);
        Qs[r * QS_STR + dq + 0] = v.x;
        Qs[r * QS_STR + dq + 1] = v.y;
        Qs[r * QS_STR + dq + 2] = v.z;
        Qs[r * QS_STR + dq + 3] = v.w;
    }
    if (tid < 64) {
        int qg = q0 + tid;
        int cum = 0, ss = 0;
        for (int i = 0; i < nseq; i++) {
            int nc = cum + seqlens[i];
            if (qg < nc) { ss = cum; break; }
            cum = nc;
        }
        seg_s[tid] = ss;
        row_m[tid] = -INFINITY;
        row_l[tid] = 0.f;
    }

    float acc[4][16];
#pragma unroll
    for (int i = 0; i < 4; i++)
#pragma unroll
        for (int j = 0; j < 16; j++) acc[i][j] = 0.f;

    __syncthreads();

    const int kt_lo = seg_s[0] >> 6;   // rows sorted => row 0 has min seg_start
    const int kt_hi = blockIdx.x;
    const int r0  = (tid >> 3) * 4;    // 4 query rows per thread
    const int c0s = (tid & 7) * 8;     // 8 score cols per thread
    const int c0v = (tid & 7) * 16;    // 16 output cols per thread

    for (int kt = kt_lo; kt <= kt_hi; kt++) {
        const int k0 = kt * 64;

        // Load K tile (stride 129) + V tile (row-major, stride 132)
#pragma unroll
        for (int t = 0; t < 16; t++) {
            int c  = t * 128 + tid;
            int r  = c >> 5;
            int dq = (c & 31) * 4;
            size_t gk = ((size_t)(k0 + r) * HKV + kvh) * HD + dq;
            float4 kv = *(const float4*)(K + gk);
            Ks[r * KS_STR + dq + 0] = kv.x;
            Ks[r * KS_STR + dq + 1] = kv.y;
            Ks[r * KS_STR + dq + 2] = kv.z;
            Ks[r * KS_STR + dq + 3] = kv.w;
            float4 vv = *(const float4*)(V + gk);
            *(float4*)&Vs[r * VS_STR + dq] = vv;
        }
        __syncthreads();

        // S = Q @ K^T  (each thread: 4x8 micro-tile)
        float sacc[4][8];
#pragma unroll
        for (int i = 0; i < 4; i++)
#pragma unroll
            for (int j = 0; j < 8; j++) sacc[i][j] = 0.f;

#pragma unroll 4
        for (int d = 0; d < HD; d++) {
            float qf[4], kf[8];
#pragma unroll
            for (int i = 0; i < 4; i++) qf[i] = Qs[(r0 + i) * QS_STR + d];
#pragma unroll
            for (int j = 0; j < 8; j++) kf[j] = Ks[(c0s + j) * KS_STR + d];
#pragma unroll
            for (int i = 0; i < 4; i++)
#pragma unroll
                for (int j = 0; j < 8; j++)
                    sacc[i][j] = fmaf(qf[i], kf[j], sacc[i][j]);
        }
#pragma unroll
        for (int i = 0; i < 4; i++)
#pragma unroll
            for (int j = 0; j < 8; j++)
                Ss[(r0 + i) * SS_STR + c0s + j] = sacc[i][j] * ATT_SCALE;
        __syncthreads();

        // Online softmax (one thread per query row)
        if (tid < 64) {
            int q  = tid;
            int qg = q0 + q;
            int ss = seg_s[q];
            float m_old = row_m[q];
            float m_new = m_old;
            for (int c = 0; c < 64; c++) {
                int kg = k0 + c;
                if (kg >= ss && kg <= qg) {
                    float x = Ss[q * SS_STR + c];
                    if (x > m_new) m_new = x;
                }
            }
            float alpha = (m_new == -INFINITY) ? 1.f : __expf(m_old - m_new);
            float l = row_l[q] * alpha;
            for (int c = 0; c < 64; c++) {
                int kg = k0 + c;
                float p = 0.f;
                if (kg >= ss && kg <= qg)
                    p = __expf(Ss[q * SS_STR + c] - m_new);
                Ss[q * SS_STR + c] = p;
                l += p;
            }
            row_m[q] = m_new;
            row_l[q] = l;
            row_a[q] = alpha;
        }
        __syncthreads();

        // acc = acc*alpha + P @ V  (each thread: 4 rows x 16 cols)
        float al[4];
#pragma unroll
        for (int i = 0; i < 4; i++) al[i] = row_a[r0 + i];
#pragma unroll
        for (int i = 0; i < 4; i++)
#pragma unroll
            for (int j = 0; j < 16; j++) acc[i][j] *= al[i];

#pragma unroll 2
        for (int k = 0; k < 64; k++) {
            float pf[4], vf[16];
#pragma unroll
            for (int i = 0; i < 4; i++) pf[i] = Ss[(r0 + i) * SS_STR + k];
            *(float4*)&vf[0]  = *(const float4*)&Vs[k * VS_STR + c0v];
            *(float4*)&vf[4]  = *(const float4*)&Vs[k * VS_STR + c0v + 4];
            *(float4*)&vf[8]  = *(const float4*)&Vs[k * VS_STR + c0v + 8];
            *(float4*)&vf[12] = *(const float4*)&Vs[k * VS_STR + c0v + 12];
#pragma unroll
            for (int i = 0; i < 4; i++)
#pragma unroll
                for (int j = 0; j < 16; j++)
                    acc[i][j] = fmaf(pf[i], vf[j], acc[i][j]);
        }
        __syncthreads();   // protect Ks/Vs/Ss before next tile
    }

    // Normalize and write O[s, h*128 + d]
#pragma unroll
    for (int i = 0; i < 4; i++) {
        float inv = 1.f / row_l[r0 + i];
        float* orow = O + (size_t)(q0 + r0 + i) * (HQ * HD) + h * HD + c0v;
#pragma unroll
        for (int j = 0; j < 16; j += 4) {
            float4 o = make_float4(acc[i][j] * inv, acc[i][j + 1] * inv,
                                   acc[i][j + 2] * inv, acc[i][j + 3] * inv);
            *(float4*)(orow + j) = o;
        }
    }
}

// ---------------------------------------------------------------------------
// Launch
// Inputs: 0:x[S,4096] 1:freqs_cis[S,64,2] 2:seqlens[int32 x nseq]
//         3:wq[4096,4096] 4:wk[1024,4096] 5:wv[1024,4096] 6:wo[4096,4096]
// Output: float32 [S, 4096]
// ---------------------------------------------------------------------------
extern "C" void kernel_launch(void* const* d_in, const int* in_sizes, int n_in,
                              void* d_out, int out_size) {
    const float* x  = (const float*)d_in[0];
    const float* fc = (const float*)d_in[1];
    const int*   sl = (const int*)d_in[2];
    const float* wq = (const float*)d_in[3];
    const float* wk = (const float*)d_in[4];
    const float* wv = (const float*)d_in[5];
    const float* wo = (const float*)d_in[6];
    float* out = (float*)d_out;

    const int S    = in_sizes[0] / DIMK;   // 2048
    const int nseq = in_sizes[2];

    float *Qp, *Kp, *Vp, *Op;
    cudaGetSymbolAddress((void**)&Qp, g_Q);
    cudaGetSymbolAddress((void**)&Kp, g_K);
    cudaGetSymbolAddress((void**)&Vp, g_V);
    cudaGetSymbolAddress((void**)&Op, g_O);

    // QKV projections
    gemm_nt<<<dim3(HQ * HD / GBN, S / GBM), 256>>>(x, wq, Qp, S, HQ * HD, DIMK);
    gemm_nt<<<dim3(HKV * HD / GBN, S / GBM), 256>>>(x, wk, Kp, S, HKV * HD, DIMK);
    gemm_nt<<<dim3(HKV * HD / GBN, S / GBM), 256>>>(x, wv, Vp, S, HKV * HD, DIMK);

    // RoPE
    {
        int tq = S * HQ * (HD / 2);
        rope_kernel<<<(tq + 255) / 256, 256>>>(Qp, fc, S, HQ);
        int tk = S * HKV * (HD / 2);
        rope_kernel<<<(tk + 255) / 256, 256>>>(Kp, fc, S, HKV);
    }

    // Attention
    cudaFuncSetAttribute(attn_kernel, cudaFuncAttributeMaxDynamicSharedMemorySize,
                         ATTN_SMEM_BYTES);
    attn_kernel<<<dim3(S / 64, HQ), 128, ATTN_SMEM_BYTES>>>(Qp, Kp, Vp, sl, nseq, Op, S);

    // Output projection
    gemm_nt<<<dim3(DIMK / GBN, S / GBM), 256>>>(Op, wo, out, S, DIMK, DIMK);
}

// round 4
// speedup vs baseline: 1.9029x; 1.9029x over previous
#include <cuda_runtime.h>
#include <cuda_bf16.h>
#include <math.h>
#include <stdint.h>

// Problem constants
#define DIMK 4096
#define HQ   32
#define HKV  8
#define HD   128
#define REP  (HQ / HKV)
#define SMAX 2048
#define ATT_SCALE 0.08838834764831845f   // 1/sqrt(128)

// ---------------------------------------------------------------------------
// Scratch (device globals: allocation-free per harness rules)
// ---------------------------------------------------------------------------
__device__ float g_Q[(size_t)SMAX * HQ * HD];
__device__ float g_K[(size_t)SMAX * HKV * HD];
__device__ float g_V[(size_t)SMAX * HKV * HD];
__device__ float g_O[(size_t)SMAX * HQ * HD];

// bf16 hi/lo split buffers
__device__ __nv_bfloat16 g_xh[(size_t)SMAX * DIMK];
__device__ __nv_bfloat16 g_xl[(size_t)SMAX * DIMK];
__device__ __nv_bfloat16 g_oh[(size_t)SMAX * DIMK];
__device__ __nv_bfloat16 g_ol[(size_t)SMAX * DIMK];
__device__ __nv_bfloat16 g_wqh[(size_t)4096 * 4096];
__device__ __nv_bfloat16 g_wql[(size_t)4096 * 4096];
__device__ __nv_bfloat16 g_wkh[(size_t)1024 * 4096];
__device__ __nv_bfloat16 g_wkl[(size_t)1024 * 4096];
__device__ __nv_bfloat16 g_wvh[(size_t)1024 * 4096];
__device__ __nv_bfloat16 g_wvl[(size_t)1024 * 4096];
__device__ __nv_bfloat16 g_woh[(size_t)4096 * 4096];
__device__ __nv_bfloat16 g_wol[(size_t)4096 * 4096];

// ---------------------------------------------------------------------------
// Helpers
// ---------------------------------------------------------------------------
static __device__ __forceinline__ uint32_t smem_u32(const void* p) {
    uint32_t a;
    asm("{ .reg .u64 t; cvta.to.shared.u64 t, %1; cvt.u32.u64 %0, t; }"
        : "=r"(a) : "l"(p));
    return a;
}

static __device__ __forceinline__ void ldsm4(uint32_t& r0, uint32_t& r1,
                                             uint32_t& r2, uint32_t& r3,
                                             uint32_t addr) {
    asm volatile("ldmatrix.sync.aligned.m8n8.x4.shared.b16 {%0,%1,%2,%3}, [%4];"
                 : "=r"(r0), "=r"(r1), "=r"(r2), "=r"(r3) : "r"(addr));
}

static __device__ __forceinline__ void mma16816(float* c, uint32_t a0, uint32_t a1,
                                                uint32_t a2, uint32_t a3,
                                                uint32_t b0, uint32_t b1) {
    asm volatile(
        "mma.sync.aligned.m16n8k16.row.col.f32.bf16.bf16.f32 "
        "{%0,%1,%2,%3}, {%4,%5,%6,%7}, {%8,%9}, {%0,%1,%2,%3};"
        : "+f"(c[0]), "+f"(c[1]), "+f"(c[2]), "+f"(c[3])
        : "r"(a0), "r"(a1), "r"(a2), "r"(a3), "r"(b0), "r"(b1));
}

// ---------------------------------------------------------------------------
// Split fp32 -> (bf16 hi, bf16 lo).  n % 4 == 0.
// ---------------------------------------------------------------------------
__global__ void split_kernel(const float* __restrict__ X,
                             __nv_bfloat16* __restrict__ H,
                             __nv_bfloat16* __restrict__ L, int n4) {
    int i = blockIdx.x * blockDim.x + threadIdx.x;
    if (i >= n4) return;
    float4 v = ((const float4*)X)[i];
    __nv_bfloat16 hx = __float2bfloat16(v.x);
    __nv_bfloat16 hy = __float2bfloat16(v.y);
    __nv_bfloat16 hz = __float2bfloat16(v.z);
    __nv_bfloat16 hw = __float2bfloat16(v.w);
    __nv_bfloat16 lx = __float2bfloat16(v.x - __bfloat162float(hx));
    __nv_bfloat16 ly = __float2bfloat16(v.y - __bfloat162float(hy));
    __nv_bfloat16 lz = __float2bfloat16(v.z - __bfloat162float(hz));
    __nv_bfloat16 lw = __float2bfloat16(v.w - __bfloat162float(hw));
    __nv_bfloat162* Hp = (__nv_bfloat162*)H;
    __nv_bfloat162* Lp = (__nv_bfloat162*)L;
    Hp[2 * i]     = __nv_bfloat162(hx, hy);
    Hp[2 * i + 1] = __nv_bfloat162(hz, hw);
    Lp[2 * i]     = __nv_bfloat162(lx, ly);
    Lp[2 * i + 1] = __nv_bfloat162(lz, lw);
}

// ---------------------------------------------------------------------------
// bf16x3 GEMM on mma.sync (HMMA): C[M,N] = (Ah+Al)[M,K] @ (Bh+Bl)[N,K]^T
// 128x128 CTA tile, BK=32, 3-stage cp.async, 8 warps (2x4), warp tile 64x32.
// M,N multiples of 128; K multiple of 32.
// ---------------------------------------------------------------------------
#define GSTAGES 3
#define GBK     32
#define RS_B    80                         // row stride in bytes (40 bf16)
#define GTILE_B (128 * RS_B)               // 10240 B per 128x32 bf16 tile
#define GSTAGE_B (4 * GTILE_B)             // Ah, Al, Bh, Bl
#define GSMEM_BYTES (GSTAGES * GSTAGE_B)   // 122880

static __device__ __forceinline__ void stage_load(uint32_t stg,
        const __nv_bfloat16* __restrict__ Ah, const __nv_bfloat16* __restrict__ Al,
        const __nv_bfloat16* __restrict__ Bh, const __nv_bfloat16* __restrict__ Bl,
        int bm, int bn, int kc, int K, int tid) {
    const __nv_bfloat16* mats[4] = {Ah, Al, Bh, Bl};
#pragma unroll
    for (int m = 0; m < 4; m++) {
        const __nv_bfloat16* src = mats[m];
        const int r0 = (m < 2) ? bm : bn;
        const uint32_t sbase = stg + m * GTILE_B;
#pragma unroll
        for (int i = 0; i < 2; i++) {
            int ch  = tid + i * 256;          // 0..511
            int r   = ch >> 2;                // 0..127
            int c16 = ch & 3;                 // 16B column (4 per row)
            uint32_t dst = sbase + (uint32_t)(r * RS_B + c16 * 16);
            const void* g = src + (size_t)(r0 + r) * K + kc + c16 * 8;
            asm volatile("cp.async.cg.shared.global [%0], [%1], 16;"
                         :: "r"(dst), "l"(g) : "memory");
        }
    }
}

__global__ __launch_bounds__(256, 1)
void gemm_bf3(const __nv_bfloat16* __restrict__ Ah, const __nv_bfloat16* __restrict__ Al,
              const __nv_bfloat16* __restrict__ Bh, const __nv_bfloat16* __restrict__ Bl,
              float* __restrict__ C, int M, int N, int K) {
    extern __shared__ __align__(16) char smraw[];
    const uint32_t sb  = smem_u32(smraw);
    const int tid  = threadIdx.x;
    const int wid  = tid >> 5;
    const int lane = tid & 31;
    const int wm   = wid >> 2;            // 0..1  (64-row slab)
    const int wn   = wid & 3;             // 0..3  (32-col slab)
    const int bm = blockIdx.y * 128;
    const int bn = blockIdx.x * 128;

    // ldmatrix per-lane offsets (within a tile)
    const int a_row = wm * 64 + (lane & 15);        // + mb*16
    const int a_colB = ((lane >> 4) * 8) * 2;       // + k0*2
    const int b_row = wn * 32 + (lane & 7) + ((lane >> 4) * 8);  // + nbp*16
    const int b_colB = (((lane >> 3) & 1) * 8) * 2; // + k0*2
    const uint32_t a_off = (uint32_t)(a_row * RS_B + a_colB);
    const uint32_t b_off = (uint32_t)(b_row * RS_B + b_colB);

    float acc[4][4][4];
#pragma unroll
    for (int i = 0; i < 4; i++)
#pragma unroll
        for (int j = 0; j < 4; j++)
#pragma unroll
            for (int k = 0; k < 4; k++) acc[i][j][k] = 0.f;

    const int NC = K / GBK;

    // Prologue: fill all stages
#pragma unroll
    for (int i = 0; i < GSTAGES; i++) {
        stage_load(sb + i * GSTAGE_B, Ah, Al, Bh, Bl, bm, bn, i * GBK, K, tid);
        asm volatile("cp.async.commit_group;" ::: "memory");
    }

    int s = 0;
    for (int c = 0; c < NC; c++) {
        asm volatile("cp.async.wait_group %0;" :: "n"(GSTAGES - 1) : "memory");
        __syncthreads();

        const uint32_t stg = sb + s * GSTAGE_B;
        // 3 passes: (Ah,Bh), (Ah,Bl), (Al,Bh)
#pragma unroll
        for (int p = 0; p < 3; p++) {
            const uint32_t At = stg + ((p == 2) ? GTILE_B : 0);
            const uint32_t Bt = stg + ((p == 1) ? 3 : 2) * GTILE_B;
#pragma unroll
            for (int k16 = 0; k16 < 2; k16++) {
                const uint32_t kB = (uint32_t)(k16 * 16 * 2);
                uint32_t a[4][4];
#pragma unroll
                for (int mb = 0; mb < 4; mb++)
                    ldsm4(a[mb][0], a[mb][1], a[mb][2], a[mb][3],
                          At + a_off + mb * (16 * RS_B) + kB);
                uint32_t b[8];
                ldsm4(b[0], b[1], b[2], b[3], Bt + b_off + kB);
                ldsm4(b[4], b[5], b[6], b[7], Bt + b_off + 16 * RS_B + kB);
#pragma unroll
                for (int mb = 0; mb < 4; mb++)
#pragma unroll
                    for (int nb = 0; nb < 4; nb++)
                        mma16816(acc[mb][nb], a[mb][0], a[mb][1], a[mb][2], a[mb][3],
                                 b[2 * nb], b[2 * nb + 1]);
            }
        }
        __syncthreads();

        const int cn = c + GSTAGES;
        if (cn < NC)
            stage_load(stg, Ah, Al, Bh, Bl, bm, bn, cn * GBK, K, tid);
        asm volatile("cp.async.commit_group;" ::: "memory");  // may be empty

        if (++s == GSTAGES) s = 0;
    }

    // Epilogue: mma.m16n8 C layout -> global
    const int tr = lane >> 2;        // 0..7
    const int tc = (lane & 3) * 2;   // 0,2,4,6
#pragma unroll
    for (int mb = 0; mb < 4; mb++) {
        const int row = bm + wm * 64 + mb * 16 + tr;
#pragma unroll
        for (int nb = 0; nb < 4; nb++) {
            const int col = bn + wn * 32 + nb * 8 + tc;
            float* c0 = C + (size_t)row * N + col;
            *(float2*)c0 = make_float2(acc[mb][nb][0], acc[mb][nb][1]);
            float* c1 = C + (size_t)(row + 8) * N + col;
            *(float2*)c1 = make_float2(acc[mb][nb][2], acc[mb][nb][3]);
        }
    }
}

// ---------------------------------------------------------------------------
// RoPE (interleaved pairs), in-place on T[S, nh, 128]
// ---------------------------------------------------------------------------
__global__ void rope_kernel(float* __restrict__ T, const float* __restrict__ fc,
                            int S, int nh) {
    int idx   = blockIdx.x * blockDim.x + threadIdx.x;
    int total = S * nh * (HD / 2);
    if (idx >= total) return;
    int i = idx & 63;
    int h = (idx >> 6) % nh;
    int s = idx / (64 * nh);
    float c  = fc[(size_t)s * HD + 2 * i];
    float sn = fc[(size_t)s * HD + 2 * i + 1];
    size_t base = ((size_t)s * nh + h) * HD + 2 * i;
    float t0 = T[base];
    float t1 = T[base + 1];
    T[base]     = t0 * c - t1 * sn;
    T[base + 1] = t0 * sn + t1 * c;
}

// ---------------------------------------------------------------------------
// Flash attention with segmented causal mask (GQA). Unchanged (passed R2).
// ---------------------------------------------------------------------------
#define QS_STR 129
#define KS_STR 129
#define VS_STR 132
#define SS_STR 65
#define ATTN_SMEM_BYTES ((64 * QS_STR + 64 * KS_STR + 64 * VS_STR + 64 * SS_STR + 3 * 64) * 4 + 64 * 4)

__global__ __launch_bounds__(128, 1)
void attn_kernel(const float* __restrict__ Q, const float* __restrict__ K,
                 const float* __restrict__ V, const int* __restrict__ seqlens,
                 int nseq, float* __restrict__ O, int S) {
    extern __shared__ __align__(16) float sm[];
    float* Qs    = sm;
    float* Ks    = Qs + 64 * QS_STR;
    float* Vs    = Ks + 64 * KS_STR;
    float* Ss    = Vs + 64 * VS_STR;
    float* row_m = Ss + 64 * SS_STR;
    float* row_l = row_m + 64;
    float* row_a = row_l + 64;
    int*   seg_s = (int*)(row_a + 64);

    const int tid = threadIdx.x;
    const int h   = blockIdx.y;
    const int kvh = h / REP;
    const int q0  = blockIdx.x * 64;

#pragma unroll
    for (int t = 0; t < 16; t++) {
        int c  = t * 128 + tid;
        int r  = c >> 5;
        int dq = (c & 31) * 4;
        float4 v = *(const float4*)(Q + ((size_t)(q0 + r) * HQ + h) * HD + dq);
        Qs[r * QS_STR + dq + 0] = v.x;
        Qs[r * QS_STR + dq + 1] = v.y;
        Qs[r * QS_STR + dq + 2] = v.z;
        Qs[r * QS_STR + dq + 3] = v.w;
    }
    if (tid < 64) {
        int qg = q0 + tid;
        int cum = 0, ss = 0;
        for (int i = 0; i < nseq; i++) {
            int nc = cum + seqlens[i];
            if (qg < nc) { ss = cum; break; }
            cum = nc;
        }
        seg_s[tid] = ss;
        row_m[tid] = -INFINITY;
        row_l[tid] = 0.f;
    }

    float acc[4][16];
#pragma unroll
    for (int i = 0; i < 4; i++)
#pragma unroll
        for (int j = 0; j < 16; j++) acc[i][j] = 0.f;

    __syncthreads();

    const int kt_lo = seg_s[0] >> 6;
    const int kt_hi = blockIdx.x;
    const int r0  = (tid >> 3) * 4;
    const int c0s = (tid & 7) * 8;
    const int c0v = (tid & 7) * 16;

    for (int kt = kt_lo; kt <= kt_hi; kt++) {
        const int k0 = kt * 64;

#pragma unroll
        for (int t = 0; t < 16; t++) {
            int c  = t * 128 + tid;
            int r  = c >> 5;
            int dq = (c & 31) * 4;
            size_t gk = ((size_t)(k0 + r) * HKV + kvh) * HD + dq;
            float4 kv = *(const float4*)(K + gk);
            Ks[r * KS_STR + dq + 0] = kv.x;
            Ks[r * KS_STR + dq + 1] = kv.y;
            Ks[r * KS_STR + dq + 2] = kv.z;
            Ks[r * KS_STR + dq + 3] = kv.w;
            float4 vv = *(const float4*)(V + gk);
            *(float4*)&Vs[r * VS_STR + dq] = vv;
        }
        __syncthreads();

        float sacc[4][8];
#pragma unroll
        for (int i = 0; i < 4; i++)
#pragma unroll
            for (int j = 0; j < 8; j++) sacc[i][j] = 0.f;

#pragma unroll 4
        for (int d = 0; d < HD; d++) {
            float qf[4], kf[8];
#pragma unroll
            for (int i = 0; i < 4; i++) qf[i] = Qs[(r0 + i) * QS_STR + d];
#pragma unroll
            for (int j = 0; j < 8; j++) kf[j] = Ks[(c0s + j) * KS_STR + d];
#pragma unroll
            for (int i = 0; i < 4; i++)
#pragma unroll
                for (int j = 0; j < 8; j++)
                    sacc[i][j] = fmaf(qf[i], kf[j], sacc[i][j]);
        }
#pragma unroll
        for (int i = 0; i < 4; i++)
#pragma unroll
            for (int j = 0; j < 8; j++)
                Ss[(r0 + i) * SS_STR + c0s + j] = sacc[i][j] * ATT_SCALE;
        __syncthreads();

        if (tid < 64) {
            int q  = tid;
            int qg = q0 + q;
            int ss = seg_s[q];
            float m_old = row_m[q];
            float m_new = m_old;
            for (int c = 0; c < 64; c++) {
                int kg = k0 + c;
                if (kg >= ss && kg <= qg) {
                    float x = Ss[q * SS_STR + c];
                    if (x > m_new) m_new = x;
                }
            }
            float alpha = (m_new == -INFINITY) ? 1.f : __expf(m_old - m_new);
            float l = row_l[q] * alpha;
            for (int c = 0; c < 64; c++) {
                int kg = k0 + c;
                float p = 0.f;
                if (kg >= ss && kg <= qg)
                    p = __expf(Ss[q * SS_STR + c] - m_new);
                Ss[q * SS_STR + c] = p;
                l += p;
            }
            row_m[q] = m_new;
            row_l[q] = l;
            row_a[q] = alpha;
        }
        __syncthreads();

        float al[4];
#pragma unroll
        for (int i = 0; i < 4; i++) al[i] = row_a[r0 + i];
#pragma unroll
        for (int i = 0; i < 4; i++)
#pragma unroll
            for (int j = 0; j < 16; j++) acc[i][j] *= al[i];

#pragma unroll 2
        for (int k = 0; k < 64; k++) {
            float pf[4], vf[16];
#pragma unroll
            for (int i = 0; i < 4; i++) pf[i] = Ss[(r0 + i) * SS_STR + k];
            *(float4*)&vf[0]  = *(const float4*)&Vs[k * VS_STR + c0v];
            *(float4*)&vf[4]  = *(const float4*)&Vs[k * VS_STR + c0v + 4];
            *(float4*)&vf[8]  = *(const float4*)&Vs[k * VS_STR + c0v + 8];
            *(float4*)&vf[12] = *(const float4*)&Vs[k * VS_STR + c0v + 12];
#pragma unroll
            for (int i = 0; i < 4; i++)
#pragma unroll
                for (int j = 0; j < 16; j++)
                    acc[i][j] = fmaf(pf[i], vf[j], acc[i][j]);
        }
        __syncthreads();
    }

#pragma unroll
    for (int i = 0; i < 4; i++) {
        float inv = 1.f / row_l[r0 + i];
        float* orow = O + (size_t)(q0 + r0 + i) * (HQ * HD) + h * HD + c0v;
#pragma unroll
        for (int j = 0; j < 16; j += 4) {
            float4 o = make_float4(acc[i][j] * inv, acc[i][j + 1] * inv,
                                   acc[i][j + 2] * inv, acc[i][j + 3] * inv);
            *(float4*)(orow + j) = o;
        }
    }
}

// ---------------------------------------------------------------------------
// Launch
// Inputs: 0:x[S,4096] 1:freqs_cis[S,64,2] 2:seqlens[int32 x nseq]
//         3:wq[4096,4096] 4:wk[1024,4096] 5:wv[1024,4096] 6:wo[4096,4096]
// Output: float32 [S, 4096]
// ---------------------------------------------------------------------------
extern "C" void kernel_launch(void* const* d_in, const int* in_sizes, int n_in,
                              void* d_out, int out_size) {
    const float* x  = (const float*)d_in[0];
    const float* fc = (const float*)d_in[1];
    const int*   sl = (const int*)d_in[2];
    const float* wq = (const float*)d_in[3];
    const float* wk = (const float*)d_in[4];
    const float* wv = (const float*)d_in[5];
    const float* wo = (const float*)d_in[6];
    float* out = (float*)d_out;

    const int S    = in_sizes[0] / DIMK;   // 2048
    const int nseq = in_sizes[2];

    float *Qp, *Kp, *Vp, *Op;
    cudaGetSymbolAddress((void**)&Qp, g_Q);
    cudaGetSymbolAddress((void**)&Kp, g_K);
    cudaGetSymbolAddress((void**)&Vp, g_V);
    cudaGetSymbolAddress((void**)&Op, g_O);

    __nv_bfloat16 *xh, *xl, *oh, *ol, *wqh, *wql, *wkh, *wkl, *wvh, *wvl, *woh, *wol;
    cudaGetSymbolAddress((void**)&xh,  g_xh);
    cudaGetSymbolAddress((void**)&xl,  g_xl);
    cudaGetSymbolAddress((void**)&oh,  g_oh);
    cudaGetSymbolAddress((void**)&ol,  g_ol);
    cudaGetSymbolAddress((void**)&wqh, g_wqh);
    cudaGetSymbolAddress((void**)&wql, g_wql);
    cudaGetSymbolAddress((void**)&wkh, g_wkh);
    cudaGetSymbolAddress((void**)&wkl, g_wkl);
    cudaGetSymbolAddress((void**)&wvh, g_wvh);
    cudaGetSymbolAddress((void**)&wvl, g_wvl);
    cudaGetSymbolAddress((void**)&woh, g_woh);
    cudaGetSymbolAddress((void**)&wol, g_wol);

    cudaFuncSetAttribute(gemm_bf3, cudaFuncAttributeMaxDynamicSharedMemorySize,
                         GSMEM_BYTES);
    cudaFuncSetAttribute(attn_kernel, cudaFuncAttributeMaxDynamicSharedMemorySize,
                         ATTN_SMEM_BYTES);

    // Split inputs / weights to bf16 hi+lo
    {
        int n;
        n = S * DIMK;       split_kernel<<<(n / 4 + 255) / 256, 256>>>(x,  xh,  xl,  n / 4);
        n = 4096 * 4096;    split_kernel<<<(n / 4 + 255) / 256, 256>>>(wq, wqh, wql, n / 4);
        n = 1024 * 4096;    split_kernel<<<(n / 4 + 255) / 256, 256>>>(wk, wkh, wkl, n / 4);
        n = 1024 * 4096;    split_kernel<<<(n / 4 + 255) / 256, 256>>>(wv, wvh, wvl, n / 4);
        n = 4096 * 4096;    split_kernel<<<(n / 4 + 255) / 256, 256>>>(wo, woh, wol, n / 4);
    }

    // QKV projections (HMMA bf16x3)
    gemm_bf3<<<dim3(4096 / 128, S / 128), 256, GSMEM_BYTES>>>(xh, xl, wqh, wql, Qp, S, 4096, DIMK);
    gemm_bf3<<<dim3(1024 / 128, S / 128), 256, GSMEM_BYTES>>>(xh, xl, wkh, wkl, Kp, S, 1024, DIMK);
    gemm_bf3<<<dim3(1024 / 128, S / 128), 256, GSMEM_BYTES>>>(xh, xl, wvh, wvl, Vp, S, 1024, DIMK);

    // RoPE
    {
        int tq = S * HQ * (HD / 2);
        rope_kernel<<<(tq + 255) / 256, 256>>>(Qp, fc, S, HQ);
        int tk = S * HKV * (HD / 2);
        rope_kernel<<<(tk + 255) / 256, 256>>>(Kp, fc, S, HKV);
    }

    // Attention
    attn_kernel<<<dim3(S / 64, HQ), 128, ATTN_SMEM_BYTES>>>(Qp, Kp, Vp, sl, nseq, Op, S);

    // Output projection
    {
        int n = S * DIMK;
        split_kernel<<<(n / 4 + 255) / 256, 256>>>(Op, oh, ol, n / 4);
        gemm_bf3<<<dim3(4096 / 128, S / 128), 256, GSMEM_BYTES>>>(oh, ol, woh, wol, out, S, 4096, DIMK);
    }
}

// round 5
// speedup vs baseline: 2.0198x; 1.0615x over previous
#include <cuda_runtime.h>
#include <cuda_bf16.h>
#include <math.h>
#include <stdint.h>

// Problem constants
#define DIMK 4096
#define HQ   32
#define HKV  8
#define HD   128
#define REP  (HQ / HKV)
#define SMAX 2048
#define ATT_SCALE 0.08838834764831845f   // 1/sqrt(128)

// ---------------------------------------------------------------------------
// Scratch (device globals: allocation-free per harness rules)
// ---------------------------------------------------------------------------
__device__ float g_Q[(size_t)SMAX * HQ * HD];
__device__ float g_K[(size_t)SMAX * HKV * HD];
__device__ float g_V[(size_t)SMAX * HKV * HD];
__device__ float g_O[(size_t)SMAX * HQ * HD];

// bf16 hi/lo split buffers
__device__ __nv_bfloat16 g_xh[(size_t)SMAX * DIMK];
__device__ __nv_bfloat16 g_xl[(size_t)SMAX * DIMK];
__device__ __nv_bfloat16 g_oh[(size_t)SMAX * DIMK];
__device__ __nv_bfloat16 g_ol[(size_t)SMAX * DIMK];
__device__ __nv_bfloat16 g_wqh[(size_t)4096 * 4096];
__device__ __nv_bfloat16 g_wql[(size_t)4096 * 4096];
__device__ __nv_bfloat16 g_wkh[(size_t)1024 * 4096];
__device__ __nv_bfloat16 g_wkl[(size_t)1024 * 4096];
__device__ __nv_bfloat16 g_wvh[(size_t)1024 * 4096];
__device__ __nv_bfloat16 g_wvl[(size_t)1024 * 4096];
__device__ __nv_bfloat16 g_woh[(size_t)4096 * 4096];
__device__ __nv_bfloat16 g_wol[(size_t)4096 * 4096];

// ---------------------------------------------------------------------------
// Helpers
// ---------------------------------------------------------------------------
static __device__ __forceinline__ uint32_t smem_u32(const void* p) {
    uint32_t a;
    asm("{ .reg .u64 t; cvta.to.shared.u64 t, %1; cvt.u32.u64 %0, t; }"
        : "=r"(a) : "l"(p));
    return a;
}

static __device__ __forceinline__ void ldsm4(uint32_t& r0, uint32_t& r1,
                                             uint32_t& r2, uint32_t& r3,
                                             uint32_t addr) {
    asm volatile("ldmatrix.sync.aligned.m8n8.x4.shared.b16 {%0,%1,%2,%3}, [%4];"
                 : "=r"(r0), "=r"(r1), "=r"(r2), "=r"(r3) : "r"(addr));
}

static __device__ __forceinline__ void mma16816(float* c, uint32_t a0, uint32_t a1,
                                                uint32_t a2, uint32_t a3,
                                                uint32_t b0, uint32_t b1) {
    asm volatile(
        "mma.sync.aligned.m16n8k16.row.col.f32.bf16.bf16.f32 "
        "{%0,%1,%2,%3}, {%4,%5,%6,%7}, {%8,%9}, {%0,%1,%2,%3};"
        : "+f"(c[0]), "+f"(c[1]), "+f"(c[2]), "+f"(c[3])
        : "r"(a0), "r"(a1), "r"(a2), "r"(a3), "r"(b0), "r"(b1));
}

// ---------------------------------------------------------------------------
// Split fp32 -> (bf16 hi, bf16 lo).  n % 4 == 0.
// ---------------------------------------------------------------------------
__global__ void split_kernel(const float* __restrict__ X,
                             __nv_bfloat16* __restrict__ H,
                             __nv_bfloat16* __restrict__ L, int n4) {
    int i = blockIdx.x * blockDim.x + threadIdx.x;
    if (i >= n4) return;
    float4 v = ((const float4*)X)[i];
    __nv_bfloat16 hx = __float2bfloat16(v.x);
    __nv_bfloat16 hy = __float2bfloat16(v.y);
    __nv_bfloat16 hz = __float2bfloat16(v.z);
    __nv_bfloat16 hw = __float2bfloat16(v.w);
    __nv_bfloat16 lx = __float2bfloat16(v.x - __bfloat162float(hx));
    __nv_bfloat16 ly = __float2bfloat16(v.y - __bfloat162float(hy));
    __nv_bfloat16 lz = __float2bfloat16(v.z - __bfloat162float(hz));
    __nv_bfloat16 lw = __float2bfloat16(v.w - __bfloat162float(hw));
    __nv_bfloat162* Hp = (__nv_bfloat162*)H;
    __nv_bfloat162* Lp = (__nv_bfloat162*)L;
    Hp[2 * i]     = __nv_bfloat162(hx, hy);
    Hp[2 * i + 1] = __nv_bfloat162(hz, hw);
    Lp[2 * i]     = __nv_bfloat162(lx, ly);
    Lp[2 * i + 1] = __nv_bfloat162(lz, lw);
}

// ---------------------------------------------------------------------------
// bf16x3 GEMM on mma.sync (HMMA): C[M,N] = (Ah+Al)[M,K] @ (Bh+Bl)[N,K]^T
// 128x128 CTA tile, BK=32, 2-stage cp.async, 8 warps (2x4), warp tile 64x32.
// 2 CTAs/SM for latency hiding.  M,N multiples of 128; K multiple of 32.
// ---------------------------------------------------------------------------
#define GSTAGES 2
#define GBK     32
#define RS_B    80                         // row stride in bytes (40 bf16)
#define GTILE_B (128 * RS_B)               // 10240 B per 128x32 bf16 tile
#define GSTAGE_B (4 * GTILE_B)             // Ah, Al, Bh, Bl
#define GSMEM_BYTES (GSTAGES * GSTAGE_B)   // 81920

static __device__ __forceinline__ void stage_load(uint32_t stg,
        const __nv_bfloat16* __restrict__ Ah, const __nv_bfloat16* __restrict__ Al,
        const __nv_bfloat16* __restrict__ Bh, const __nv_bfloat16* __restrict__ Bl,
        int bm, int bn, int kc, int K, int tid) {
    const __nv_bfloat16* mats[4] = {Ah, Al, Bh, Bl};
#pragma unroll
    for (int m = 0; m < 4; m++) {
        const __nv_bfloat16* src = mats[m];
        const int r0 = (m < 2) ? bm : bn;
        const uint32_t sbase = stg + m * GTILE_B;
#pragma unroll
        for (int i = 0; i < 2; i++) {
            int ch  = tid + i * 256;          // 0..511
            int r   = ch >> 2;                // 0..127
            int c16 = ch & 3;                 // 16B column (4 per row)
            uint32_t dst = sbase + (uint32_t)(r * RS_B + c16 * 16);
            const void* g = src + (size_t)(r0 + r) * K + kc + c16 * 8;
            asm volatile("cp.async.cg.shared.global [%0], [%1], 16;"
                         :: "r"(dst), "l"(g) : "memory");
        }
    }
}

__global__ __launch_bounds__(256, 2)
void gemm_bf3(const __nv_bfloat16* __restrict__ Ah, const __nv_bfloat16* __restrict__ Al,
              const __nv_bfloat16* __restrict__ Bh, const __nv_bfloat16* __restrict__ Bl,
              float* __restrict__ C, int M, int N, int K) {
    extern __shared__ __align__(16) char smraw[];
    const uint32_t sb  = smem_u32(smraw);
    const int tid  = threadIdx.x;
    const int wid  = tid >> 5;
    const int lane = tid & 31;
    const int wm   = wid >> 2;            // 0..1  (64-row slab)
    const int wn   = wid & 3;             // 0..3  (32-col slab)
    const int bm = blockIdx.y * 128;
    const int bn = blockIdx.x * 128;

    // ldmatrix per-lane offsets (within a tile)
    const int a_row = wm * 64 + (lane & 15);        // + mb*16
    const int a_colB = ((lane >> 4) * 8) * 2;       // + k0*2
    const int b_row = wn * 32 + (lane & 7) + ((lane >> 4) * 8);  // + nbp*16
    const int b_colB = (((lane >> 3) & 1) * 8) * 2; // + k0*2
    const uint32_t a_off = (uint32_t)(a_row * RS_B + a_colB);
    const uint32_t b_off = (uint32_t)(b_row * RS_B + b_colB);

    float acc[4][4][4];
#pragma unroll
    for (int i = 0; i < 4; i++)
#pragma unroll
        for (int j = 0; j < 4; j++)
#pragma unroll
            for (int k = 0; k < 4; k++) acc[i][j][k] = 0.f;

    const int NC = K / GBK;

    // Prologue: fill both stages
#pragma unroll
    for (int i = 0; i < GSTAGES; i++) {
        stage_load(sb + i * GSTAGE_B, Ah, Al, Bh, Bl, bm, bn, i * GBK, K, tid);
        asm volatile("cp.async.commit_group;" ::: "memory");
    }

    int s = 0;
    for (int c = 0; c < NC; c++) {
        asm volatile("cp.async.wait_group %0;" :: "n"(GSTAGES - 1) : "memory");
        __syncthreads();

        const uint32_t stg = sb + s * GSTAGE_B;
        // 3 passes: (Ah,Bh), (Ah,Bl), (Al,Bh)
#pragma unroll
        for (int p = 0; p < 3; p++) {
            const uint32_t At = stg + ((p == 2) ? GTILE_B : 0);
            const uint32_t Bt = stg + ((p == 1) ? 3 : 2) * GTILE_B;
#pragma unroll
            for (int k16 = 0; k16 < 2; k16++) {
                const uint32_t kB = (uint32_t)(k16 * 16 * 2);
                uint32_t a[4][4];
#pragma unroll
                for (int mb = 0; mb < 4; mb++)
                    ldsm4(a[mb][0], a[mb][1], a[mb][2], a[mb][3],
                          At + a_off + mb * (16 * RS_B) + kB);
                uint32_t b[8];
                ldsm4(b[0], b[1], b[2], b[3], Bt + b_off + kB);
                ldsm4(b[4], b[5], b[6], b[7], Bt + b_off + 16 * RS_B + kB);
#pragma unroll
                for (int mb = 0; mb < 4; mb++)
#pragma unroll
                    for (int nb = 0; nb < 4; nb++)
                        mma16816(acc[mb][nb], a[mb][0], a[mb][1], a[mb][2], a[mb][3],
                                 b[2 * nb], b[2 * nb + 1]);
            }
        }
        __syncthreads();

        const int cn = c + GSTAGES;
        if (cn < NC)
            stage_load(stg, Ah, Al, Bh, Bl, bm, bn, cn * GBK, K, tid);
        asm volatile("cp.async.commit_group;" ::: "memory");  // may be empty

        if (++s == GSTAGES) s = 0;
    }

    // Epilogue: mma.m16n8 C layout -> global
    const int tr = lane >> 2;        // 0..7
    const int tc = (lane & 3) * 2;   // 0,2,4,6
#pragma unroll
    for (int mb = 0; mb < 4; mb++) {
        const int row = bm + wm * 64 + mb * 16 + tr;
#pragma unroll
        for (int nb = 0; nb < 4; nb++) {
            const int col = bn + wn * 32 + nb * 8 + tc;
            float* c0 = C + (size_t)row * N + col;
            *(float2*)c0 = make_float2(acc[mb][nb][0], acc[mb][nb][1]);
            float* c1 = C + (size_t)(row + 8) * N + col;
            *(float2*)c1 = make_float2(acc[mb][nb][2], acc[mb][nb][3]);
        }
    }
}

// ---------------------------------------------------------------------------
// RoPE (interleaved pairs), in-place on T[S, nh, 128]
// ---------------------------------------------------------------------------
__global__ void rope_kernel(float* __restrict__ T, const float* __restrict__ fc,
                            int S, int nh) {
    int idx   = blockIdx.x * blockDim.x + threadIdx.x;
    int total = S * nh * (HD / 2);
    if (idx >= total) return;
    int i = idx & 63;
    int h = (idx >> 6) % nh;
    int s = idx / (64 * nh);
    float c  = fc[(size_t)s * HD + 2 * i];
    float sn = fc[(size_t)s * HD + 2 * i + 1];
    size_t base = ((size_t)s * nh + h) * HD + 2 * i;
    float t0 = T[base];
    float t1 = T[base + 1];
    T[base]     = t0 * c - t1 * sn;
    T[base + 1] = t0 * sn + t1 * c;
}

// ---------------------------------------------------------------------------
// Flash attention with segmented causal mask (GQA). Unchanged (FFMA-bound).
// ---------------------------------------------------------------------------
#define QS_STR 129
#define KS_STR 129
#define VS_STR 132
#define SS_STR 65
#define ATTN_SMEM_BYTES ((64 * QS_STR + 64 * KS_STR + 64 * VS_STR + 64 * SS_STR + 3 * 64) * 4 + 64 * 4)

__global__ __launch_bounds__(128, 1)
void attn_kernel(const float* __restrict__ Q, const float* __restrict__ K,
                 const float* __restrict__ V, const int* __restrict__ seqlens,
                 int nseq, float* __restrict__ O, int S) {
    extern __shared__ __align__(16) float sm[];
    float* Qs    = sm;
    float* Ks    = Qs + 64 * QS_STR;
    float* Vs    = Ks + 64 * KS_STR;
    float* Ss    = Vs + 64 * VS_STR;
    float* row_m = Ss + 64 * SS_STR;
    float* row_l = row_m + 64;
    float* row_a = row_l + 64;
    int*   seg_s = (int*)(row_a + 64);

    const int tid = threadIdx.x;
    const int h   = blockIdx.y;
    const int kvh = h / REP;
    const int q0  = blockIdx.x * 64;

#pragma unroll
    for (int t = 0; t < 16; t++) {
        int c  = t * 128 + tid;
        int r  = c >> 5;
        int dq = (c & 31) * 4;
        float4 v = *(const float4*)(Q + ((size_t)(q0 + r) * HQ + h) * HD + dq);
        Qs[r * QS_STR + dq + 0] = v.x;
        Qs[r * QS_STR + dq + 1] = v.y;
        Qs[r * QS_STR + dq + 2] = v.z;
        Qs[r * QS_STR + dq + 3] = v.w;
    }
    if (tid < 64) {
        int qg = q0 + tid;
        int cum = 0, ss = 0;
        for (int i = 0; i < nseq; i++) {
            int nc = cum + seqlens[i];
            if (qg < nc) { ss = cum; break; }
            cum = nc;
        }
        seg_s[tid] = ss;
        row_m[tid] = -INFINITY;
        row_l[tid] = 0.f;
    }

    float acc[4][16];
#pragma unroll
    for (int i = 0; i < 4; i++)
#pragma unroll
        for (int j = 0; j < 16; j++) acc[i][j] = 0.f;

    __syncthreads();

    const int kt_lo = seg_s[0] >> 6;
    const int kt_hi = blockIdx.x;
    const int r0  = (tid >> 3) * 4;
    const int c0s = (tid & 7) * 8;
    const int c0v = (tid & 7) * 16;

    for (int kt = kt_lo; kt <= kt_hi; kt++) {
        const int k0 = kt * 64;

#pragma unroll
        for (int t = 0; t < 16; t++) {
            int c  = t * 128 + tid;
            int r  = c >> 5;
            int dq = (c & 31) * 4;
            size_t gk = ((size_t)(k0 + r) * HKV + kvh) * HD + dq;
            float4 kv = *(const float4*)(K + gk);
            Ks[r * KS_STR + dq + 0] = kv.x;
            Ks[r * KS_STR + dq + 1] = kv.y;
            Ks[r * KS_STR + dq + 2] = kv.z;
            Ks[r * KS_STR + dq + 3] = kv.w;
            float4 vv = *(const float4*)(V + gk);
            *(float4*)&Vs[r * VS_STR + dq] = vv;
        }
        __syncthreads();

        float sacc[4][8];
#pragma unroll
        for (int i = 0; i < 4; i++)
#pragma unroll
            for (int j = 0; j < 8; j++) sacc[i][j] = 0.f;

#pragma unroll 4
        for (int d = 0; d < HD; d++) {
            float qf[4], kf[8];
#pragma unroll
            for (int i = 0; i < 4; i++) qf[i] = Qs[(r0 + i) * QS_STR + d];
#pragma unroll
            for (int j = 0; j < 8; j++) kf[j] = Ks[(c0s + j) * KS_STR + d];
#pragma unroll
            for (int i = 0; i < 4; i++)
#pragma unroll
                for (int j = 0; j < 8; j++)
                    sacc[i][j] = fmaf(qf[i], kf[j], sacc[i][j]);
        }
#pragma unroll
        for (int i = 0; i < 4; i++)
#pragma unroll
            for (int j = 0; j < 8; j++)
                Ss[(r0 + i) * SS_STR + c0s + j] = sacc[i][j] * ATT_SCALE;
        __syncthreads();

        if (tid < 64) {
            int q  = tid;
            int qg = q0 + q;
            int ss = seg_s[q];
            float m_old = row_m[q];
            float m_new = m_old;
            for (int c = 0; c < 64; c++) {
                int kg = k0 + c;
                if (kg >= ss && kg <= qg) {
                    float x = Ss[q * SS_STR + c];
                    if (x > m_new) m_new = x;
                }
            }
            float alpha = (m_new == -INFINITY) ? 1.f : __expf(m_old - m_new);
            float l = row_l[q] * alpha;
            for (int c = 0; c < 64; c++) {
                int kg = k0 + c;
                float p = 0.f;
                if (kg >= ss && kg <= qg)
                    p = __expf(Ss[q * SS_STR + c] - m_new);
                Ss[q * SS_STR + c] = p;
                l += p;
            }
            row_m[q] = m_new;
            row_l[q] = l;
            row_a[q] = alpha;
        }
        __syncthreads();

        float al[4];
#pragma unroll
        for (int i = 0; i < 4; i++) al[i] = row_a[r0 + i];
#pragma unroll
        for (int i = 0; i < 4; i++)
#pragma unroll
            for (int j = 0; j < 16; j++) acc[i][j] *= al[i];

#pragma unroll 2
        for (int k = 0; k < 64; k++) {
            float pf[4], vf[16];
#pragma unroll
            for (int i = 0; i < 4; i++) pf[i] = Ss[(r0 + i) * SS_STR + k];
            *(float4*)&vf[0]  = *(const float4*)&Vs[k * VS_STR + c0v];
            *(float4*)&vf[4]  = *(const float4*)&Vs[k * VS_STR + c0v + 4];
            *(float4*)&vf[8]  = *(const float4*)&Vs[k * VS_STR + c0v + 8];
            *(float4*)&vf[12] = *(const float4*)&Vs[k * VS_STR + c0v + 12];
#pragma unroll
            for (int i = 0; i < 4; i++)
#pragma unroll
                for (int j = 0; j < 16; j++)
                    acc[i][j] = fmaf(pf[i], vf[j], acc[i][j]);
        }
        __syncthreads();
    }

#pragma unroll
    for (int i = 0; i < 4; i++) {
        float inv = 1.f / row_l[r0 + i];
        float* orow = O + (size_t)(q0 + r0 + i) * (HQ * HD) + h * HD + c0v;
#pragma unroll
        for (int j = 0; j < 16; j += 4) {
            float4 o = make_float4(acc[i][j] * inv, acc[i][j + 1] * inv,
                                   acc[i][j + 2] * inv, acc[i][j + 3] * inv);
            *(float4*)(orow + j) = o;
        }
    }
}

// ---------------------------------------------------------------------------
// Launch
// Inputs: 0:x[S,4096] 1:freqs_cis[S,64,2] 2:seqlens[int32 x nseq]
//         3:wq[4096,4096] 4:wk[1024,4096] 5:wv[1024,4096] 6:wo[4096,4096]
// Output: float32 [S, 4096]
// ---------------------------------------------------------------------------
extern "C" void kernel_launch(void* const* d_in, const int* in_sizes, int n_in,
                              void* d_out, int out_size) {
    const float* x  = (const float*)d_in[0];
    const float* fc = (const float*)d_in[1];
    const int*   sl = (const int*)d_in[2];
    const float* wq = (const float*)d_in[3];
    const float* wk = (const float*)d_in[4];
    const float* wv = (const float*)d_in[5];
    const float* wo = (const float*)d_in[6];
    float* out = (float*)d_out;

    const int S    = in_sizes[0] / DIMK;   // 2048
    const int nseq = in_sizes[2];

    float *Qp, *Kp, *Vp, *Op;
    cudaGetSymbolAddress((void**)&Qp, g_Q);
    cudaGetSymbolAddress((void**)&Kp, g_K);
    cudaGetSymbolAddress((void**)&Vp, g_V);
    cudaGetSymbolAddress((void**)&Op, g_O);

    __nv_bfloat16 *xh, *xl, *oh, *ol, *wqh, *wql, *wkh, *wkl, *wvh, *wvl, *woh, *wol;
    cudaGetSymbolAddress((void**)&xh,  g_xh);
    cudaGetSymbolAddress((void**)&xl,  g_xl);
    cudaGetSymbolAddress((void**)&oh,  g_oh);
    cudaGetSymbolAddress((void**)&ol,  g_ol);
    cudaGetSymbolAddress((void**)&wqh, g_wqh);
    cudaGetSymbolAddress((void**)&wql, g_wql);
    cudaGetSymbolAddress((void**)&wkh, g_wkh);
    cudaGetSymbolAddress((void**)&wkl, g_wkl);
    cudaGetSymbolAddress((void**)&wvh, g_wvh);
    cudaGetSymbolAddress((void**)&wvl, g_wvl);
    cudaGetSymbolAddress((void**)&woh, g_woh);
    cudaGetSymbolAddress((void**)&wol, g_wol);

    cudaFuncSetAttribute(gemm_bf3, cudaFuncAttributeMaxDynamicSharedMemorySize,
                         GSMEM_BYTES);
    cudaFuncSetAttribute(attn_kernel, cudaFuncAttributeMaxDynamicSharedMemorySize,
                         ATTN_SMEM_BYTES);

    // Split inputs / weights to bf16 hi+lo
    {
        int n;
        n = S * DIMK;       split_kernel<<<(n / 4 + 255) / 256, 256>>>(x,  xh,  xl,  n / 4);
        n = 4096 * 4096;    split_kernel<<<(n / 4 + 255) / 256, 256>>>(wq, wqh, wql, n / 4);
        n = 1024 * 4096;    split_kernel<<<(n / 4 + 255) / 256, 256>>>(wk, wkh, wkl, n / 4);
        n = 1024 * 4096;    split_kernel<<<(n / 4 + 255) / 256, 256>>>(wv, wvh, wvl, n / 4);
        n = 4096 * 4096;    split_kernel<<<(n / 4 + 255) / 256, 256>>>(wo, woh, wol, n / 4);
    }

    // QKV projections (HMMA bf16x3)
    gemm_bf3<<<dim3(4096 / 128, S / 128), 256, GSMEM_BYTES>>>(xh, xl, wqh, wql, Qp, S, 4096, DIMK);
    gemm_bf3<<<dim3(1024 / 128, S / 128), 256, GSMEM_BYTES>>>(xh, xl, wkh, wkl, Kp, S, 1024, DIMK);
    gemm_bf3<<<dim3(1024 / 128, S / 128), 256, GSMEM_BYTES>>>(xh, xl, wvh, wvl, Vp, S, 1024, DIMK);

    // RoPE
    {
        int tq = S * HQ * (HD / 2);
        rope_kernel<<<(tq + 255) / 256, 256>>>(Qp, fc, S, HQ);
        int tk = S * HKV * (HD / 2);
        rope_kernel<<<(tk + 255) / 256, 256>>>(Kp, fc, S, HKV);
    }

    // Attention
    attn_kernel<<<dim3(S / 64, HQ), 128, ATTN_SMEM_BYTES>>>(Qp, Kp, Vp, sl, nseq, Op, S);

    // Output projection
    {
        int n = S * DIMK;
        split_kernel<<<(n / 4 + 255) / 256, 256>>>(Op, oh, ol, n / 4);
        gemm_bf3<<<dim3(4096 / 128, S / 128), 256, GSMEM_BYTES>>>(oh, ol, woh, wol, out, S, 4096, DIMK);
    }
}

// round 7
// speedup vs baseline: 2.6169x; 1.2956x over previous
#include <cuda_runtime.h>
#include <cuda_fp16.h>
#include <math.h>
#include <stdint.h>

// Problem constants
#define DIMK 4096
#define HQ   32
#define HKV  8
#define HD   128
#define REP  (HQ / HKV)
#define SMAX 2048
#define ATT_SCALE 0.08838834764831845f   // 1/sqrt(128)
#define W_SCALE   1024.0f
#define W_UNSCALE 0.0009765625f          // 2^-10

// ---------------------------------------------------------------------------
// Scratch (device globals: allocation-free per harness rules)
// ---------------------------------------------------------------------------
__device__ float g_Q[(size_t)SMAX * HQ * HD];
__device__ float g_K[(size_t)SMAX * HKV * HD];
__device__ float g_V[(size_t)SMAX * HKV * HD];
__device__ float g_O[(size_t)SMAX * HQ * HD];

// fp16 buffers: activations (hi only) + weights (hi/lo, pre-scaled by 1024)
__device__ __half g_xh[(size_t)SMAX * DIMK];
__device__ __half g_oh[(size_t)SMAX * DIMK];
__device__ __half g_wqh[(size_t)4096 * 4096];
__device__ __half g_wql[(size_t)4096 * 4096];
__device__ __half g_wkh[(size_t)1024 * 4096];
__device__ __half g_wkl[(size_t)1024 * 4096];
__device__ __half g_wvh[(size_t)1024 * 4096];
__device__ __half g_wvl[(size_t)1024 * 4096];
__device__ __half g_woh[(size_t)4096 * 4096];
__device__ __half g_wol[(size_t)4096 * 4096];

// ---------------------------------------------------------------------------
// Helpers
// ---------------------------------------------------------------------------
static __device__ __forceinline__ uint32_t smem_u32(const void* p) {
    uint32_t a;
    asm("{ .reg .u64 t; cvta.to.shared.u64 t, %1; cvt.u32.u64 %0, t; }"
        : "=r"(a) : "l"(p));
    return a;
}

static __device__ __forceinline__ void ldsm4(uint32_t& r0, uint32_t& r1,
                                             uint32_t& r2, uint32_t& r3,
                                             uint32_t addr) {
    asm volatile("ldmatrix.sync.aligned.m8n8.x4.shared.b16 {%0,%1,%2,%3}, [%4];"
                 : "=r"(r0), "=r"(r1), "=r"(r2), "=r"(r3) : "r"(addr));
}

static __device__ __forceinline__ void mma16816(float* c, uint32_t a0, uint32_t a1,
                                                uint32_t a2, uint32_t a3,
                                                uint32_t b0, uint32_t b1) {
    asm volatile(
        "mma.sync.aligned.m16n8k16.row.col.f32.f16.f16.f32 "
        "{%0,%1,%2,%3}, {%4,%5,%6,%7}, {%8,%9}, {%0,%1,%2,%3};"
        : "+f"(c[0]), "+f"(c[1]), "+f"(c[2]), "+f"(c[3])
        : "r"(a0), "r"(a1), "r"(a2), "r"(a3), "r"(b0), "r"(b1));
}

// ---------------------------------------------------------------------------
// Cast fp32 -> fp16 (activation hi).  n % 4 == 0.
// ---------------------------------------------------------------------------
__global__ void cast_kernel(const float* __restrict__ X,
                            __half* __restrict__ H, int n4) {
    int i = blockIdx.x * blockDim.x + threadIdx.x;
    if (i >= n4) return;
    float4 v = ((const float4*)X)[i];
    __half2* Hp = (__half2*)H;
    Hp[2 * i]     = __floats2half2_rn(v.x, v.y);
    Hp[2 * i + 1] = __floats2half2_rn(v.z, v.w);
}

// ---------------------------------------------------------------------------
// Split fp32 weight -> (fp16 hi, fp16 lo), pre-scaled by 1024 (subnormal guard)
// ---------------------------------------------------------------------------
__global__ void split_w_kernel(const float* __restrict__ X,
                               __half* __restrict__ H,
                               __half* __restrict__ L, int n4) {
    int i = blockIdx.x * blockDim.x + threadIdx.x;
    if (i >= n4) return;
    float4 v = ((const float4*)X)[i];
    float sx = v.x * W_SCALE, sy = v.y * W_SCALE;
    float sz = v.z * W_SCALE, sw = v.w * W_SCALE;
    __half hx = __float2half_rn(sx);
    __half hy = __float2half_rn(sy);
    __half hz = __float2half_rn(sz);
    __half hw = __float2half_rn(sw);
    __half lx = __float2half_rn(sx - __half2float(hx));
    __half ly = __float2half_rn(sy - __half2float(hy));
    __half lz = __float2half_rn(sz - __half2float(hz));
    __half lw = __float2half_rn(sw - __half2float(hw));
    __half2* Hp = (__half2*)H;
    __half2* Lp = (__half2*)L;
    Hp[2 * i]     = __half2(hx, hy);
    Hp[2 * i + 1] = __half2(hz, hw);
    Lp[2 * i]     = __half2(lx, ly);
    Lp[2 * i + 1] = __half2(lz, lw);
}

// ---------------------------------------------------------------------------
// fp16x2 GEMM on mma.sync: C[M,N] = (1/1024) * A[M,K] @ (Bh+Bl)[N,K]^T
// 128x128 CTA tile, BK=32, 3-stage cp.async, 8 warps (2x4), warp tile 64x32.
// 2 passes (A*Bh + A*Bl), 2 CTAs/SM.  M,N mult of 128; K mult of 32.
// ---------------------------------------------------------------------------
#define GSTAGES 3
#define GBK     32
#define RS_B    80                         // row stride in bytes (40 fp16)
#define GTILE_B (128 * RS_B)               // 10240 B per 128x32 fp16 tile
#define GSTAGE_B (3 * GTILE_B)             // A, Bh, Bl
#define GSMEM_BYTES (GSTAGES * GSTAGE_B)   // 92160

static __device__ __forceinline__ void stage_load(uint32_t stg,
        const __half* __restrict__ A, const __half* __restrict__ Bh,
        const __half* __restrict__ Bl,
        int bm, int bn, int kc, int K, int tid) {
    const __half* mats[3] = {A, Bh, Bl};
#pragma unroll
    for (int m = 0; m < 3; m++) {
        const __half* src = mats[m];
        const int r0 = (m < 1) ? bm : bn;
        const uint32_t sbase = stg + m * GTILE_B;
#pragma unroll
        for (int i = 0; i < 2; i++) {
            int ch  = tid + i * 256;          // 0..511
            int r   = ch >> 2;                // 0..127
            int c16 = ch & 3;                 // 16B column (4 per row)
            uint32_t dst = sbase + (uint32_t)(r * RS_B + c16 * 16);
            const void* g = src + (size_t)(r0 + r) * K + kc + c16 * 8;
            asm volatile("cp.async.cg.shared.global [%0], [%1], 16;"
                         :: "r"(dst), "l"(g) : "memory");
        }
    }
}

__global__ __launch_bounds__(256, 2)
void gemm_f16x2(const __half* __restrict__ A, const __half* __restrict__ Bh,
                const __half* __restrict__ Bl,
                float* __restrict__ C, int M, int N, int K) {
    extern __shared__ __align__(16) char smraw[];
    const uint32_t sb  = smem_u32(smraw);
    const int tid  = threadIdx.x;
    const int wid  = tid >> 5;
    const int lane = tid & 31;
    const int wm   = wid >> 2;            // 0..1  (64-row slab)
    const int wn   = wid & 3;             // 0..3  (32-col slab)
    const int bm = blockIdx.y * 128;
    const int bn = blockIdx.x * 128;

    // ldmatrix per-lane offsets (within a tile)
    const int a_row = wm * 64 + (lane & 15);        // + mb*16
    const int a_colB = ((lane >> 4) * 8) * 2;       // + k0*2
    const int b_row = wn * 32 + (lane & 7) + ((lane >> 4) * 8);  // + nbp*16
    const int b_colB = (((lane >> 3) & 1) * 8) * 2; // + k0*2
    const uint32_t a_off = (uint32_t)(a_row * RS_B + a_colB);
    const uint32_t b_off = (uint32_t)(b_row * RS_B + b_colB);

    float acc[4][4][4];
#pragma unroll
    for (int i = 0; i < 4; i++)
#pragma unroll
        for (int j = 0; j < 4; j++)
#pragma unroll
            for (int k = 0; k < 4; k++) acc[i][j][k] = 0.f;

    const int NC = K / GBK;

    // Prologue: fill all stages
#pragma unroll
    for (int i = 0; i < GSTAGES; i++) {
        stage_load(sb + i * GSTAGE_B, A, Bh, Bl, bm, bn, i * GBK, K, tid);
        asm volatile("cp.async.commit_group;" ::: "memory");
    }

    int s = 0;
    for (int c = 0; c < NC; c++) {
        asm volatile("cp.async.wait_group %0;" :: "n"(GSTAGES - 1) : "memory");
        __syncthreads();

        const uint32_t stg = sb + s * GSTAGE_B;
#pragma unroll
        for (int k16 = 0; k16 < 2; k16++) {
            const uint32_t kB = (uint32_t)(k16 * 16 * 2);
            // A fragments (shared across both passes)
            uint32_t a[4][4];
#pragma unroll
            for (int mb = 0; mb < 4; mb++)
                ldsm4(a[mb][0], a[mb][1], a[mb][2], a[mb][3],
                      stg + a_off + mb * (16 * RS_B) + kB);
            // 2 passes: Bh, Bl
#pragma unroll
            for (int p = 0; p < 2; p++) {
                const uint32_t Bt = stg + (1 + p) * GTILE_B;
                uint32_t b[8];
                ldsm4(b[0], b[1], b[2], b[3], Bt + b_off + kB);
                ldsm4(b[4], b[5], b[6], b[7], Bt + b_off + 16 * RS_B + kB);
#pragma unroll
                for (int mb = 0; mb < 4; mb++)
#pragma unroll
                    for (int nb = 0; nb < 4; nb++)
                        mma16816(acc[mb][nb], a[mb][0], a[mb][1], a[mb][2], a[mb][3],
                                 b[2 * nb], b[2 * nb + 1]);
            }
        }
        __syncthreads();

        const int cn = c + GSTAGES;
        if (cn < NC)
            stage_load(sb + s * GSTAGE_B, A, Bh, Bl, bm, bn, cn * GBK, K, tid);
        asm volatile("cp.async.commit_group;" ::: "memory");  // may be empty

        if (++s == GSTAGES) s = 0;
    }

    // Epilogue: undo the weight 1024x pre-scale, store
    const int tr = lane >> 2;        // 0..7
    const int tc = (lane & 3) * 2;   // 0,2,4,6
#pragma unroll
    for (int mb = 0; mb < 4; mb++) {
        const int row = bm + wm * 64 + mb * 16 + tr;
#pragma unroll
        for (int nb = 0; nb < 4; nb++) {
            const int col = bn + wn * 32 + nb * 8 + tc;
            float* c0 = C + (size_t)row * N + col;
            *(float2*)c0 = make_float2(acc[mb][nb][0] * W_UNSCALE,
                                       acc[mb][nb][1] * W_UNSCALE);
            float* c1 = C + (size_t)(row + 8) * N + col;
            *(float2*)c1 = make_float2(acc[mb][nb][2] * W_UNSCALE,
                                       acc[mb][nb][3] * W_UNSCALE);
        }
    }
}

// ---------------------------------------------------------------------------
// RoPE (interleaved pairs), in-place on T[S, nh, 128]
// ---------------------------------------------------------------------------
__global__ void rope_kernel(float* __restrict__ T, const float* __restrict__ fc,
                            int S, int nh) {
    int idx   = blockIdx.x * blockDim.x + threadIdx.x;
    int total = S * nh * (HD / 2);
    if (idx >= total) return;
    int i = idx & 63;
    int h = (idx >> 6) % nh;
    int s = idx / (64 * nh);
    float c  = fc[(size_t)s * HD + 2 * i];
    float sn = fc[(size_t)s * HD + 2 * i + 1];
    size_t base = ((size_t)s * nh + h) * HD + 2 * i;
    float t0 = T[base];
    float t1 = T[base + 1];
    T[base]     = t0 * c - t1 * sn;
    T[base + 1] = t0 * sn + t1 * c;
}

// ---------------------------------------------------------------------------
// Flash attention with segmented causal mask (GQA). Unchanged (FFMA-bound).
// ---------------------------------------------------------------------------
#define QS_STR 129
#define KS_STR 129
#define VS_STR 132
#define SS_STR 65
#define ATTN_SMEM_BYTES ((64 * QS_STR + 64 * KS_STR + 64 * VS_STR + 64 * SS_STR + 3 * 64) * 4 + 64 * 4)

__global__ __launch_bounds__(128, 1)
void attn_kernel(const float* __restrict__ Q, const float* __restrict__ K,
                 const float* __restrict__ V, const int* __restrict__ seqlens,
                 int nseq, float* __restrict__ O, int S) {
    extern __shared__ __align__(16) float sm[];
    float* Qs    = sm;
    float* Ks    = Qs + 64 * QS_STR;
    float* Vs    = Ks + 64 * KS_STR;
    float* Ss    = Vs + 64 * VS_STR;
    float* row_m = Ss + 64 * SS_STR;
    float* row_l = row_m + 64;
    float* row_a = row_l + 64;
    int*   seg_s = (int*)(row_a + 64);

    const int tid = threadIdx.x;
    const int h   = blockIdx.y;
    const int kvh = h / REP;
    const int q0  = blockIdx.x * 64;

#pragma unroll
    for (int t = 0; t < 16; t++) {
        int c  = t * 128 + tid;
        int r  = c >> 5;
        int dq = (c & 31) * 4;
        float4 v = *(const float4*)(Q + ((size_t)(q0 + r) * HQ + h) * HD + dq);
        Qs[r * QS_STR + dq + 0] = v.x;
        Qs[r * QS_STR + dq + 1] = v.y;
        Qs[r * QS_STR + dq + 2] = v.z;
        Qs[r * QS_STR + dq + 3] = v.w;
    }
    if (tid < 64) {
        int qg = q0 + tid;
        int cum = 0, ss = 0;
        for (int i = 0; i < nseq; i++) {
            int nc = cum + seqlens[i];
            if (qg < nc) { ss = cum; break; }
            cum = nc;
        }
        seg_s[tid] = ss;
        row_m[tid] = -INFINITY;
        row_l[tid] = 0.f;
    }

    float acc[4][16];
#pragma unroll
    for (int i = 0; i < 4; i++)
#pragma unroll
        for (int j = 0; j < 16; j++) acc[i][j] = 0.f;

    __syncthreads();

    const int kt_lo = seg_s[0] >> 6;
    const int kt_hi = blockIdx.x;
    const int r0  = (tid >> 3) * 4;
    const int c0s = (tid & 7) * 8;
    const int c0v = (tid & 7) * 16;

    for (int kt = kt_lo; kt <= kt_hi; kt++) {
        const int k0 = kt * 64;

#pragma unroll
        for (int t = 0; t < 16; t++) {
            int c  = t * 128 + tid;
            int r  = c >> 5;
            int dq = (c & 31) * 4;
            size_t gk = ((size_t)(k0 + r) * HKV + kvh) * HD + dq;
            float4 kv = *(const float4*)(K + gk);
            Ks[r * KS_STR + dq + 0] = kv.x;
            Ks[r * KS_STR + dq + 1] = kv.y;
            Ks[r * KS_STR + dq + 2] = kv.z;
            Ks[r * KS_STR + dq + 3] = kv.w;
            float4 vv = *(const float4*)(V + gk);
            *(float4*)&Vs[r * VS_STR + dq] = vv;
        }
        __syncthreads();

        float sacc[4][8];
#pragma unroll
        for (int i = 0; i < 4; i++)
#pragma unroll
            for (int j = 0; j < 8; j++) sacc[i][j] = 0.f;

#pragma unroll 4
        for (int d = 0; d < HD; d++) {
            float qf[4], kf[8];
#pragma unroll
            for (int i = 0; i < 4; i++) qf[i] = Qs[(r0 + i) * QS_STR + d];
#pragma unroll
            for (int j = 0; j < 8; j++) kf[j] = Ks[(c0s + j) * KS_STR + d];
#pragma unroll
            for (int i = 0; i < 4; i++)
#pragma unroll
                for (int j = 0; j < 8; j++)
                    sacc[i][j] = fmaf(qf[i], kf[j], sacc[i][j]);
        }
#pragma unroll
        for (int i = 0; i < 4; i++)
#pragma unroll
            for (int j = 0; j < 8; j++)
                Ss[(r0 + i) * SS_STR + c0s + j] = sacc[i][j] * ATT_SCALE;
        __syncthreads();

        if (tid < 64) {
            int q  = tid;
            int qg = q0 + q;
            int ss = seg_s[q];
            float m_old = row_m[q];
            float m_new = m_old;
            for (int c = 0; c < 64; c++) {
                int kg = k0 + c;
                if (kg >= ss && kg <= qg) {
                    float x = Ss[q * SS_STR + c];
                    if (x > m_new) m_new = x;
                }
            }
            float alpha = (m_new == -INFINITY) ? 1.f : __expf(m_old - m_new);
            float l = row_l[q] * alpha;
            for (int c = 0; c < 64; c++) {
                int kg = k0 + c;
                float p = 0.f;
                if (kg >= ss && kg <= qg)
                    p = __expf(Ss[q * SS_STR + c] - m_new);
                Ss[q * SS_STR + c] = p;
                l += p;
            }
            row_m[q] = m_new;
            row_l[q] = l;
            row_a[q] = alpha;
        }
        __syncthreads();

        float al[4];
#pragma unroll
        for (int i = 0; i < 4; i++) al[i] = row_a[r0 + i];
#pragma unroll
        for (int i = 0; i < 4; i++)
#pragma unroll
            for (int j = 0; j < 16; j++) acc[i][j] *= al[i];

#pragma unroll 2
        for (int k = 0; k < 64; k++) {
            float pf[4], vf[16];
#pragma unroll
            for (int i = 0; i < 4; i++) pf[i] = Ss[(r0 + i) * SS_STR + k];
            *(float4*)&vf[0]  = *(const float4*)&Vs[k * VS_STR + c0v];
            *(float4*)&vf[4]  = *(const float4*)&Vs[k * VS_STR + c0v + 4];
            *(float4*)&vf[8]  = *(const float4*)&Vs[k * VS_STR + c0v + 8];
            *(float4*)&vf[12] = *(const float4*)&Vs[k * VS_STR + c0v + 12];
#pragma unroll
            for (int i = 0; i < 4; i++)
#pragma unroll
                for (int j = 0; j < 16; j++)
                    acc[i][j] = fmaf(pf[i], vf[j], acc[i][j]);
        }
        __syncthreads();
    }

#pragma unroll
    for (int i = 0; i < 4; i++) {
        float inv = 1.f / row_l[r0 + i];
        float* orow = O + (size_t)(q0 + r0 + i) * (HQ * HD) + h * HD + c0v;
#pragma unroll
        for (int j = 0; j < 16; j += 4) {
            float4 o = make_float4(acc[i][j] * inv, acc[i][j + 1] * inv,
                                   acc[i][j + 2] * inv, acc[i][j + 3] * inv);
            *(float4*)(orow + j) = o;
        }
    }
}

// ---------------------------------------------------------------------------
// Launch
// Inputs: 0:x[S,4096] 1:freqs_cis[S,64,2] 2:seqlens[int32 x nseq]
//         3:wq[4096,4096] 4:wk[1024,4096] 5:wv[1024,4096] 6:wo[4096,4096]
// Output: float32 [S, 4096]
// ---------------------------------------------------------------------------
extern "C" void kernel_launch(void* const* d_in, const int* in_sizes, int n_in,
                              void* d_out, int out_size) {
    const float* x  = (const float*)d_in[0];
    const float* fc = (const float*)d_in[1];
    const int*   sl = (const int*)d_in[2];
    const float* wq = (const float*)d_in[3];
    const float* wk = (const float*)d_in[4];
    const float* wv = (const float*)d_in[5];
    const float* wo = (const float*)d_in[6];
    float* out = (float*)d_out;

    const int S    = in_sizes[0] / DIMK;   // 2048
    const int nseq = in_sizes[2];

    float *Qp, *Kp, *Vp, *Op;
    cudaGetSymbolAddress((void**)&Qp, g_Q);
    cudaGetSymbolAddress((void**)&Kp, g_K);
    cudaGetSymbolAddress((void**)&Vp, g_V);
    cudaGetSymbolAddress((void**)&Op, g_O);

    __half *xh, *oh, *wqh, *wql, *wkh, *wkl, *wvh, *wvl, *woh, *wol;
    cudaGetSymbolAddress((void**)&xh,  g_xh);
    cudaGetSymbolAddress((void**)&oh,  g_oh);
    cudaGetSymbolAddress((void**)&wqh, g_wqh);
    cudaGetSymbolAddress((void**)&wql, g_wql);
    cudaGetSymbolAddress((void**)&wkh, g_wkh);
    cudaGetSymbolAddress((void**)&wkl, g_wkl);
    cudaGetSymbolAddress((void**)&wvh, g_wvh);
    cudaGetSymbolAddress((void**)&wvl, g_wvl);
    cudaGetSymbolAddress((void**)&woh, g_woh);
    cudaGetSymbolAddress((void**)&wol, g_wol);

    cudaFuncSetAttribute(gemm_f16x2, cudaFuncAttributeMaxDynamicSharedMemorySize,
                         GSMEM_BYTES);
    cudaFuncSetAttribute(attn_kernel, cudaFuncAttributeMaxDynamicSharedMemorySize,
                         ATTN_SMEM_BYTES);

    // Cast activations; split weights (pre-scaled by 1024)
    {
        int n;
        n = S * DIMK;       cast_kernel<<<(n / 4 + 255) / 256, 256>>>(x, xh, n / 4);
        n = 4096 * 4096;    split_w_kernel<<<(n / 4 + 255) / 256, 256>>>(wq, wqh, wql, n / 4);
        n = 1024 * 4096;    split_w_kernel<<<(n / 4 + 255) / 256, 256>>>(wk, wkh, wkl, n / 4);
        n = 1024 * 4096;    split_w_kernel<<<(n / 4 + 255) / 256, 256>>>(wv, wvh, wvl, n / 4);
        n = 4096 * 4096;    split_w_kernel<<<(n / 4 + 255) / 256, 256>>>(wo, woh, wol, n / 4);
    }

    // QKV projections (HMMA fp16x2)
    gemm_f16x2<<<dim3(4096 / 128, S / 128), 256, GSMEM_BYTES>>>(xh, wqh, wql, Qp, S, 4096, DIMK);
    gemm_f16x2<<<dim3(1024 / 128, S / 128), 256, GSMEM_BYTES>>>(xh, wkh, wkl, Kp, S, 1024, DIMK);
    gemm_f16x2<<<dim3(1024 / 128, S / 128), 256, GSMEM_BYTES>>>(xh, wvh, wvl, Vp, S, 1024, DIMK);

    // RoPE
    {
        int tq = S * HQ * (HD / 2);
        rope_kernel<<<(tq + 255) / 256, 256>>>(Qp, fc, S, HQ);
        int tk = S * HKV * (HD / 2);
        rope_kernel<<<(tk + 255) / 256, 256>>>(Kp, fc, S, HKV);
    }

    // Attention (fp32, unchanged)
    attn_kernel<<<dim3(S / 64, HQ), 128, ATTN_SMEM_BYTES>>>(Qp, Kp, Vp, sl, nseq, Op, S);

    // Output projection
    {
        int n = S * DIMK;
        cast_kernel<<<(n / 4 + 255) / 256, 256>>>(Op, oh, n / 4);
        gemm_f16x2<<<dim3(4096 / 128, S / 128), 256, GSMEM_BYTES>>>(oh, woh, wol, out, S, 4096, DIMK);
    }
}

// round 8
// speedup vs baseline: 2.9378x; 1.1226x over previous
#include <cuda_runtime.h>
#include <cuda_fp16.h>
#include <math.h>
#include <stdint.h>

// Problem constants
#define DIMK 4096
#define HQ   32
#define HKV  8
#define HD   128
#define REP  (HQ / HKV)
#define SMAX 2048
#define ATT_SCALE 0.08838834764831845f   // 1/sqrt(128)
#define W_SCALE   1024.0f
#define W_UNSCALE 0.0009765625f          // 2^-10

// ---------------------------------------------------------------------------
// Scratch (device globals: allocation-free per harness rules)
// ---------------------------------------------------------------------------
__device__ float g_Q[(size_t)SMAX * HQ * HD];
__device__ float g_K[(size_t)SMAX * HKV * HD];
__device__ float g_V[(size_t)SMAX * HKV * HD];
__device__ float g_O[(size_t)SMAX * HQ * HD];

// fp16 buffers
__device__ __half g_xh[(size_t)SMAX * DIMK];
__device__ __half g_oh[(size_t)SMAX * DIMK];
__device__ __half g_wqh[(size_t)4096 * 4096];   // scaled x1024, hi
__device__ __half g_wql[(size_t)4096 * 4096];   // scaled x1024, lo
__device__ __half g_wkh[(size_t)1024 * 4096];
__device__ __half g_wkl[(size_t)1024 * 4096];
__device__ __half g_wvh[(size_t)1024 * 4096];   // plain fp16 (single-pass)
__device__ __half g_woh[(size_t)4096 * 4096];   // plain fp16 (single-pass)

// ---------------------------------------------------------------------------
// Helpers
// ---------------------------------------------------------------------------
static __device__ __forceinline__ uint32_t smem_u32(const void* p) {
    uint32_t a;
    asm("{ .reg .u64 t; cvta.to.shared.u64 t, %1; cvt.u32.u64 %0, t; }"
        : "=r"(a) : "l"(p));
    return a;
}

static __device__ __forceinline__ void ldsm4(uint32_t& r0, uint32_t& r1,
                                             uint32_t& r2, uint32_t& r3,
                                             uint32_t addr) {
    asm volatile("ldmatrix.sync.aligned.m8n8.x4.shared.b16 {%0,%1,%2,%3}, [%4];"
                 : "=r"(r0), "=r"(r1), "=r"(r2), "=r"(r3) : "r"(addr));
}

static __device__ __forceinline__ void mma16816(float* c, uint32_t a0, uint32_t a1,
                                                uint32_t a2, uint32_t a3,
                                                uint32_t b0, uint32_t b1) {
    asm volatile(
        "mma.sync.aligned.m16n8k16.row.col.f32.f16.f16.f32 "
        "{%0,%1,%2,%3}, {%4,%5,%6,%7}, {%8,%9}, {%0,%1,%2,%3};"
        : "+f"(c[0]), "+f"(c[1]), "+f"(c[2]), "+f"(c[3])
        : "r"(a0), "r"(a1), "r"(a2), "r"(a3), "r"(b0), "r"(b1));
}

// ---------------------------------------------------------------------------
// Cast fp32 -> fp16.  n % 4 == 0.
// ---------------------------------------------------------------------------
__global__ void cast_kernel(const float* __restrict__ X,
                            __half* __restrict__ H, int n4) {
    int i = blockIdx.x * blockDim.x + threadIdx.x;
    if (i >= n4) return;
    float4 v = ((const float4*)X)[i];
    __half2* Hp = (__half2*)H;
    Hp[2 * i]     = __floats2half2_rn(v.x, v.y);
    Hp[2 * i + 1] = __floats2half2_rn(v.z, v.w);
}

// ---------------------------------------------------------------------------
// Split fp32 weight -> (fp16 hi, fp16 lo), pre-scaled by 1024 (subnormal guard)
// ---------------------------------------------------------------------------
__global__ void split_w_kernel(const float* __restrict__ X,
                               __half* __restrict__ H,
                               __half* __restrict__ L, int n4) {
    int i = blockIdx.x * blockDim.x + threadIdx.x;
    if (i >= n4) return;
    float4 v = ((const float4*)X)[i];
    float sx = v.x * W_SCALE, sy = v.y * W_SCALE;
    float sz = v.z * W_SCALE, sw = v.w * W_SCALE;
    __half hx = __float2half_rn(sx);
    __half hy = __float2half_rn(sy);
    __half hz = __float2half_rn(sz);
    __half hw = __float2half_rn(sw);
    __half lx = __float2half_rn(sx - __half2float(hx));
    __half ly = __float2half_rn(sy - __half2float(hy));
    __half lz = __float2half_rn(sz - __half2float(hz));
    __half lw = __float2half_rn(sw - __half2float(hw));
    __half2* Hp = (__half2*)H;
    __half2* Lp = (__half2*)L;
    Hp[2 * i]     = __half2(hx, hy);
    Hp[2 * i + 1] = __half2(hz, hw);
    Lp[2 * i]     = __half2(lx, ly);
    Lp[2 * i + 1] = __half2(lz, lw);
}

// ---------------------------------------------------------------------------
// Shared GEMM geometry: 128x128 CTA tile, BK=32, 8 warps (2x4), warp 64x32.
// ---------------------------------------------------------------------------
#define GSTAGES 3
#define GBK     32
#define RS_B    80                         // row stride in bytes (40 fp16)
#define GTILE_B (128 * RS_B)               // 10240 B per 128x32 fp16 tile
#define GSTAGE3_B (3 * GTILE_B)            // A, Bh, Bl  (2-pass kernel)
#define GSMEM3_BYTES (GSTAGES * GSTAGE3_B) // 92160
#define GSTAGE2_B (2 * GTILE_B)            // A, B       (1-pass kernel)
#define GSMEM2_BYTES (GSTAGES * GSTAGE2_B) // 61440

static __device__ __forceinline__ void tile_cp(uint32_t sbase,
        const __half* __restrict__ src, int r0, int kc, int K, int tid) {
#pragma unroll
    for (int i = 0; i < 2; i++) {
        int ch  = tid + i * 256;          // 0..511
        int r   = ch >> 2;                // 0..127
        int c16 = ch & 3;                 // 16B column (4 per row)
        uint32_t dst = sbase + (uint32_t)(r * RS_B + c16 * 16);
        const void* g = src + (size_t)(r0 + r) * K + kc + c16 * 8;
        asm volatile("cp.async.cg.shared.global [%0], [%1], 16;"
                     :: "r"(dst), "l"(g) : "memory");
    }
}

// ---------------------------------------------------------------------------
// 2-pass GEMM: C = (1/1024) * A @ (Bh+Bl)^T
// ---------------------------------------------------------------------------
__global__ __launch_bounds__(256, 2)
void gemm_f16x2(const __half* __restrict__ A, const __half* __restrict__ Bh,
                const __half* __restrict__ Bl,
                float* __restrict__ C, int M, int N, int K) {
    extern __shared__ __align__(16) char smraw[];
    const uint32_t sb  = smem_u32(smraw);
    const int tid  = threadIdx.x;
    const int wid  = tid >> 5;
    const int lane = tid & 31;
    const int wm   = wid >> 2;
    const int wn   = wid & 3;
    const int bm = blockIdx.y * 128;
    const int bn = blockIdx.x * 128;

    const int a_row = wm * 64 + (lane & 15);
    const int a_colB = ((lane >> 4) * 8) * 2;
    const int b_row = wn * 32 + (lane & 7) + ((lane >> 4) * 8);
    const int b_colB = (((lane >> 3) & 1) * 8) * 2;
    const uint32_t a_off = (uint32_t)(a_row * RS_B + a_colB);
    const uint32_t b_off = (uint32_t)(b_row * RS_B + b_colB);

    float acc[4][4][4];
#pragma unroll
    for (int i = 0; i < 4; i++)
#pragma unroll
        for (int j = 0; j < 4; j++)
#pragma unroll
            for (int k = 0; k < 4; k++) acc[i][j][k] = 0.f;

    const int NC = K / GBK;

#pragma unroll
    for (int i = 0; i < GSTAGES; i++) {
        const uint32_t stg = sb + i * GSTAGE3_B;
        tile_cp(stg,               A,  bm, i * GBK, K, tid);
        tile_cp(stg + GTILE_B,     Bh, bn, i * GBK, K, tid);
        tile_cp(stg + 2 * GTILE_B, Bl, bn, i * GBK, K, tid);
        asm volatile("cp.async.commit_group;" ::: "memory");
    }

    int s = 0;
    for (int c = 0; c < NC; c++) {
        asm volatile("cp.async.wait_group %0;" :: "n"(GSTAGES - 1) : "memory");
        __syncthreads();

        const uint32_t stg = sb + s * GSTAGE3_B;
#pragma unroll
        for (int k16 = 0; k16 < 2; k16++) {
            const uint32_t kB = (uint32_t)(k16 * 16 * 2);
            uint32_t a[4][4];
#pragma unroll
            for (int mb = 0; mb < 4; mb++)
                ldsm4(a[mb][0], a[mb][1], a[mb][2], a[mb][3],
                      stg + a_off + mb * (16 * RS_B) + kB);
#pragma unroll
            for (int p = 0; p < 2; p++) {
                const uint32_t Bt = stg + (1 + p) * GTILE_B;
                uint32_t b[8];
                ldsm4(b[0], b[1], b[2], b[3], Bt + b_off + kB);
                ldsm4(b[4], b[5], b[6], b[7], Bt + b_off + 16 * RS_B + kB);
#pragma unroll
                for (int mb = 0; mb < 4; mb++)
#pragma unroll
                    for (int nb = 0; nb < 4; nb++)
                        mma16816(acc[mb][nb], a[mb][0], a[mb][1], a[mb][2], a[mb][3],
                                 b[2 * nb], b[2 * nb + 1]);
            }
        }
        __syncthreads();

        const int cn = c + GSTAGES;
        if (cn < NC) {
            const uint32_t stg2 = sb + s * GSTAGE3_B;
            tile_cp(stg2,               A,  bm, cn * GBK, K, tid);
            tile_cp(stg2 + GTILE_B,     Bh, bn, cn * GBK, K, tid);
            tile_cp(stg2 + 2 * GTILE_B, Bl, bn, cn * GBK, K, tid);
        }
        asm volatile("cp.async.commit_group;" ::: "memory");

        if (++s == GSTAGES) s = 0;
    }

    const int tr = lane >> 2;
    const int tc = (lane & 3) * 2;
#pragma unroll
    for (int mb = 0; mb < 4; mb++) {
        const int row = bm + wm * 64 + mb * 16 + tr;
#pragma unroll
        for (int nb = 0; nb < 4; nb++) {
            const int col = bn + wn * 32 + nb * 8 + tc;
            float* c0 = C + (size_t)row * N + col;
            *(float2*)c0 = make_float2(acc[mb][nb][0] * W_UNSCALE,
                                       acc[mb][nb][1] * W_UNSCALE);
            float* c1 = C + (size_t)(row + 8) * N + col;
            *(float2*)c1 = make_float2(acc[mb][nb][2] * W_UNSCALE,
                                       acc[mb][nb][3] * W_UNSCALE);
        }
    }
}

// ---------------------------------------------------------------------------
// 1-pass GEMM: C = A @ B^T   (plain fp16 weights, no scaling)
// ---------------------------------------------------------------------------
__global__ __launch_bounds__(256, 2)
void gemm_f16(const __half* __restrict__ A, const __half* __restrict__ B,
              float* __restrict__ C, int M, int N, int K) {
    extern __shared__ __align__(16) char smraw[];
    const uint32_t sb  = smem_u32(smraw);
    const int tid  = threadIdx.x;
    const int wid  = tid >> 5;
    const int lane = tid & 31;
    const int wm   = wid >> 2;
    const int wn   = wid & 3;
    const int bm = blockIdx.y * 128;
    const int bn = blockIdx.x * 128;

    const int a_row = wm * 64 + (lane & 15);
    const int a_colB = ((lane >> 4) * 8) * 2;
    const int b_row = wn * 32 + (lane & 7) + ((lane >> 4) * 8);
    const int b_colB = (((lane >> 3) & 1) * 8) * 2;
    const uint32_t a_off = (uint32_t)(a_row * RS_B + a_colB);
    const uint32_t b_off = (uint32_t)(b_row * RS_B + b_colB);

    float acc[4][4][4];
#pragma unroll
    for (int i = 0; i < 4; i++)
#pragma unroll
        for (int j = 0; j < 4; j++)
#pragma unroll
            for (int k = 0; k < 4; k++) acc[i][j][k] = 0.f;

    const int NC = K / GBK;

#pragma unroll
    for (int i = 0; i < GSTAGES; i++) {
        const uint32_t stg = sb + i * GSTAGE2_B;
        tile_cp(stg,           A, bm, i * GBK, K, tid);
        tile_cp(stg + GTILE_B, B, bn, i * GBK, K, tid);
        asm volatile("cp.async.commit_group;" ::: "memory");
    }

    int s = 0;
    for (int c = 0; c < NC; c++) {
        asm volatile("cp.async.wait_group %0;" :: "n"(GSTAGES - 1) : "memory");
        __syncthreads();

        const uint32_t stg = sb + s * GSTAGE2_B;
        const uint32_t Bt  = stg + GTILE_B;
#pragma unroll
        for (int k16 = 0; k16 < 2; k16++) {
            const uint32_t kB = (uint32_t)(k16 * 16 * 2);
            uint32_t a[4][4];
#pragma unroll
            for (int mb = 0; mb < 4; mb++)
                ldsm4(a[mb][0], a[mb][1], a[mb][2], a[mb][3],
                      stg + a_off + mb * (16 * RS_B) + kB);
            uint32_t b[8];
            ldsm4(b[0], b[1], b[2], b[3], Bt + b_off + kB);
            ldsm4(b[4], b[5], b[6], b[7], Bt + b_off + 16 * RS_B + kB);
#pragma unroll
            for (int mb = 0; mb < 4; mb++)
#pragma unroll
                for (int nb = 0; nb < 4; nb++)
                    mma16816(acc[mb][nb], a[mb][0], a[mb][1], a[mb][2], a[mb][3],
                             b[2 * nb], b[2 * nb + 1]);
        }
        __syncthreads();

        const int cn = c + GSTAGES;
        if (cn < NC) {
            const uint32_t stg2 = sb + s * GSTAGE2_B;
            tile_cp(stg2,           A, bm, cn * GBK, K, tid);
            tile_cp(stg2 + GTILE_B, B, bn, cn * GBK, K, tid);
        }
        asm volatile("cp.async.commit_group;" ::: "memory");

        if (++s == GSTAGES) s = 0;
    }

    const int tr = lane >> 2;
    const int tc = (lane & 3) * 2;
#pragma unroll
    for (int mb = 0; mb < 4; mb++) {
        const int row = bm + wm * 64 + mb * 16 + tr;
#pragma unroll
        for (int nb = 0; nb < 4; nb++) {
            const int col = bn + wn * 32 + nb * 8 + tc;
            float* c0 = C + (size_t)row * N + col;
            *(float2*)c0 = make_float2(acc[mb][nb][0], acc[mb][nb][1]);
            float* c1 = C + (size_t)(row + 8) * N + col;
            *(float2*)c1 = make_float2(acc[mb][nb][2], acc[mb][nb][3]);
        }
    }
}

// ---------------------------------------------------------------------------
// RoPE (interleaved pairs), in-place on T[S, nh, 128]
// ---------------------------------------------------------------------------
__global__ void rope_kernel(float* __restrict__ T, const float* __restrict__ fc,
                            int S, int nh) {
    int idx   = blockIdx.x * blockDim.x + threadIdx.x;
    int total = S * nh * (HD / 2);
    if (idx >= total) return;
    int i = idx & 63;
    int h = (idx >> 6) % nh;
    int s = idx / (64 * nh);
    float c  = fc[(size_t)s * HD + 2 * i];
    float sn = fc[(size_t)s * HD + 2 * i + 1];
    size_t base = ((size_t)s * nh + h) * HD + 2 * i;
    float t0 = T[base];
    float t1 = T[base + 1];
    T[base]     = t0 * c - t1 * sn;
    T[base + 1] = t0 * sn + t1 * c;
}

// ---------------------------------------------------------------------------
// Flash attention with segmented causal mask (GQA). Unchanged.
// ---------------------------------------------------------------------------
#define QS_STR 129
#define KS_STR 129
#define VS_STR 132
#define SS_STR 65
#define ATTN_SMEM_BYTES ((64 * QS_STR + 64 * KS_STR + 64 * VS_STR + 64 * SS_STR + 3 * 64) * 4 + 64 * 4)

__global__ __launch_bounds__(128, 1)
void attn_kernel(const float* __restrict__ Q, const float* __restrict__ K,
                 const float* __restrict__ V, const int* __restrict__ seqlens,
                 int nseq, float* __restrict__ O, int S) {
    extern __shared__ __align__(16) float sm[];
    float* Qs    = sm;
    float* Ks    = Qs + 64 * QS_STR;
    float* Vs    = Ks + 64 * KS_STR;
    float* Ss    = Vs + 64 * VS_STR;
    float* row_m = Ss + 64 * SS_STR;
    float* row_l = row_m + 64;
    float* row_a = row_l + 64;
    int*   seg_s = (int*)(row_a + 64);

    const int tid = threadIdx.x;
    const int h   = blockIdx.y;
    const int kvh = h / REP;
    const int q0  = blockIdx.x * 64;

#pragma unroll
    for (int t = 0; t < 16; t++) {
        int c  = t * 128 + tid;
        int r  = c >> 5;
        int dq = (c & 31) * 4;
        float4 v = *(const float4*)(Q + ((size_t)(q0 + r) * HQ + h) * HD + dq);
        Qs[r * QS_STR + dq + 0] = v.x;
        Qs[r * QS_STR + dq + 1] = v.y;
        Qs[r * QS_STR + dq + 2] = v.z;
        Qs[r * QS_STR + dq + 3] = v.w;
    }
    if (tid < 64) {
        int qg = q0 + tid;
        int cum = 0, ss = 0;
        for (int i = 0; i < nseq; i++) {
            int nc = cum + seqlens[i];
            if (qg < nc) { ss = cum; break; }
            cum = nc;
        }
        seg_s[tid] = ss;
        row_m[tid] = -INFINITY;
        row_l[tid] = 0.f;
    }

    float acc[4][16];
#pragma unroll
    for (int i = 0; i < 4; i++)
#pragma unroll
        for (int j = 0; j < 16; j++) acc[i][j] = 0.f;

    __syncthreads();

    const int kt_lo = seg_s[0] >> 6;
    const int kt_hi = blockIdx.x;
    const int r0  = (tid >> 3) * 4;
    const int c0s = (tid & 7) * 8;
    const int c0v = (tid & 7) * 16;

    for (int kt = kt_lo; kt <= kt_hi; kt++) {
        const int k0 = kt * 64;

#pragma unroll
        for (int t = 0; t < 16; t++) {
            int c  = t * 128 + tid;
            int r  = c >> 5;
            int dq = (c & 31) * 4;
            size_t gk = ((size_t)(k0 + r) * HKV + kvh) * HD + dq;
            float4 kv = *(const float4*)(K + gk);
            Ks[r * KS_STR + dq + 0] = kv.x;
            Ks[r * KS_STR + dq + 1] = kv.y;
            Ks[r * KS_STR + dq + 2] = kv.z;
            Ks[r * KS_STR + dq + 3] = kv.w;
            float4 vv = *(const float4*)(V + gk);
            *(float4*)&Vs[r * VS_STR + dq] = vv;
        }
        __syncthreads();

        float sacc[4][8];
#pragma unroll
        for (int i = 0; i < 4; i++)
#pragma unroll
            for (int j = 0; j < 8; j++) sacc[i][j] = 0.f;

#pragma unroll 4
        for (int d = 0; d < HD; d++) {
            float qf[4], kf[8];
#pragma unroll
            for (int i = 0; i < 4; i++) qf[i] = Qs[(r0 + i) * QS_STR + d];
#pragma unroll
            for (int j = 0; j < 8; j++) kf[j] = Ks[(c0s + j) * KS_STR + d];
#pragma unroll
            for (int i = 0; i < 4; i++)
#pragma unroll
                for (int j = 0; j < 8; j++)
                    sacc[i][j] = fmaf(qf[i], kf[j], sacc[i][j]);
        }
#pragma unroll
        for (int i = 0; i < 4; i++)
#pragma unroll
            for (int j = 0; j < 8; j++)
                Ss[(r0 + i) * SS_STR + c0s + j] = sacc[i][j] * ATT_SCALE;
        __syncthreads();

        if (tid < 64) {
            int q  = tid;
            int qg = q0 + q;
            int ss = seg_s[q];
            float m_old = row_m[q];
            float m_new = m_old;
            for (int c = 0; c < 64; c++) {
                int kg = k0 + c;
                if (kg >= ss && kg <= qg) {
                    float x = Ss[q * SS_STR + c];
                    if (x > m_new) m_new = x;
                }
            }
            float alpha = (m_new == -INFINITY) ? 1.f : __expf(m_old - m_new);
            float l = row_l[q] * alpha;
            for (int c = 0; c < 64; c++) {
                int kg = k0 + c;
                float p = 0.f;
                if (kg >= ss && kg <= qg)
                    p = __expf(Ss[q * SS_STR + c] - m_new);
                Ss[q * SS_STR + c] = p;
                l += p;
            }
            row_m[q] = m_new;
            row_l[q] = l;
            row_a[q] = alpha;
        }
        __syncthreads();

        float al[4];
#pragma unroll
        for (int i = 0; i < 4; i++) al[i] = row_a[r0 + i];
#pragma unroll
        for (int i = 0; i < 4; i++)
#pragma unroll
            for (int j = 0; j < 16; j++) acc[i][j] *= al[i];

#pragma unroll 2
        for (int k = 0; k < 64; k++) {
            float pf[4], vf[16];
#pragma unroll
            for (int i = 0; i < 4; i++) pf[i] = Ss[(r0 + i) * SS_STR + k];
            *(float4*)&vf[0]  = *(const float4*)&Vs[k * VS_STR + c0v];
            *(float4*)&vf[4]  = *(const float4*)&Vs[k * VS_STR + c0v + 4];
            *(float4*)&vf[8]  = *(const float4*)&Vs[k * VS_STR + c0v + 8];
            *(float4*)&vf[12] = *(const float4*)&Vs[k * VS_STR + c0v + 12];
#pragma unroll
            for (int i = 0; i < 4; i++)
#pragma unroll
                for (int j = 0; j < 16; j++)
                    acc[i][j] = fmaf(pf[i], vf[j], acc[i][j]);
        }
        __syncthreads();
    }

#pragma unroll
    for (int i = 0; i < 4; i++) {
        float inv = 1.f / row_l[r0 + i];
        float* orow = O + (size_t)(q0 + r0 + i) * (HQ * HD) + h * HD + c0v;
#pragma unroll
        for (int j = 0; j < 16; j += 4) {
            float4 o = make_float4(acc[i][j] * inv, acc[i][j + 1] * inv,
                                   acc[i][j + 2] * inv, acc[i][j + 3] * inv);
            *(float4*)(orow + j) = o;
        }
    }
}

// ---------------------------------------------------------------------------
// Launch
// Inputs: 0:x[S,4096] 1:freqs_cis[S,64,2] 2:seqlens[int32 x nseq]
//         3:wq[4096,4096] 4:wk[1024,4096] 5:wv[1024,4096] 6:wo[4096,4096]
// Output: float32 [S, 4096]
// ---------------------------------------------------------------------------
extern "C" void kernel_launch(void* const* d_in, const int* in_sizes, int n_in,
                              void* d_out, int out_size) {
    const float* x  = (const float*)d_in[0];
    const float* fc = (const float*)d_in[1];
    const int*   sl = (const int*)d_in[2];
    const float* wq = (const float*)d_in[3];
    const float* wk = (const float*)d_in[4];
    const float* wv = (const float*)d_in[5];
    const float* wo = (const float*)d_in[6];
    float* out = (float*)d_out;

    const int S    = in_sizes[0] / DIMK;   // 2048
    const int nseq = in_sizes[2];

    float *Qp, *Kp, *Vp, *Op;
    cudaGetSymbolAddress((void**)&Qp, g_Q);
    cudaGetSymbolAddress((void**)&Kp, g_K);
    cudaGetSymbolAddress((void**)&Vp, g_V);
    cudaGetSymbolAddress((void**)&Op, g_O);

    __half *xh, *oh, *wqh, *wql, *wkh, *wkl, *wvh, *woh;
    cudaGetSymbolAddress((void**)&xh,  g_xh);
    cudaGetSymbolAddress((void**)&oh,  g_oh);
    cudaGetSymbolAddress((void**)&wqh, g_wqh);
    cudaGetSymbolAddress((void**)&wql, g_wql);
    cudaGetSymbolAddress((void**)&wkh, g_wkh);
    cudaGetSymbolAddress((void**)&wkl, g_wkl);
    cudaGetSymbolAddress((void**)&wvh, g_wvh);
    cudaGetSymbolAddress((void**)&woh, g_woh);

    cudaFuncSetAttribute(gemm_f16x2, cudaFuncAttributeMaxDynamicSharedMemorySize,
                         GSMEM3_BYTES);
    cudaFuncSetAttribute(gemm_f16, cudaFuncAttributeMaxDynamicSharedMemorySize,
                         GSMEM2_BYTES);
    cudaFuncSetAttribute(attn_kernel, cudaFuncAttributeMaxDynamicSharedMemorySize,
                         ATTN_SMEM_BYTES);

    // Cast activations; split wq/wk (scaled), cast wv/wo (plain fp16)
    {
        int n;
        n = S * DIMK;       cast_kernel<<<(n / 4 + 255) / 256, 256>>>(x, xh, n / 4);
        n = 4096 * 4096;    split_w_kernel<<<(n / 4 + 255) / 256, 256>>>(wq, wqh, wql, n / 4);
        n = 1024 * 4096;    split_w_kernel<<<(n / 4 + 255) / 256, 256>>>(wk, wkh, wkl, n / 4);
        n = 1024 * 4096;    cast_kernel<<<(n / 4 + 255) / 256, 256>>>(wv, wvh, n / 4);
        n = 4096 * 4096;    cast_kernel<<<(n / 4 + 255) / 256, 256>>>(wo, woh, n / 4);
    }

    // QKV projections
    gemm_f16x2<<<dim3(4096 / 128, S / 128), 256, GSMEM3_BYTES>>>(xh, wqh, wql, Qp, S, 4096, DIMK);
    gemm_f16x2<<<dim3(1024 / 128, S / 128), 256, GSMEM3_BYTES>>>(xh, wkh, wkl, Kp, S, 1024, DIMK);
    gemm_f16<<<dim3(1024 / 128, S / 128), 256, GSMEM2_BYTES>>>(xh, wvh, Vp, S, 1024, DIMK);

    // RoPE
    {
        int tq = S * HQ * (HD / 2);
        rope_kernel<<<(tq + 255) / 256, 256>>>(Qp, fc, S, HQ);
        int tk = S * HKV * (HD / 2);
        rope_kernel<<<(tk + 255) / 256, 256>>>(Kp, fc, S, HKV);
    }

    // Attention (fp32, unchanged)
    attn_kernel<<<dim3(S / 64, HQ), 128, ATTN_SMEM_BYTES>>>(Qp, Kp, Vp, sl, nseq, Op, S);

    // Output projection (single-pass fp16)
    {
        int n = S * DIMK;
        cast_kernel<<<(n / 4 + 255) / 256, 256>>>(Op, oh, n / 4);
        gemm_f16<<<dim3(4096 / 128, S / 128), 256, GSMEM2_BYTES>>>(oh, woh, out, S, 4096, DIMK);
    }
}

// round 9
// speedup vs baseline: 5.0116x; 1.7059x over previous
#include <cuda_runtime.h>
#include <cuda_fp16.h>
#include <math.h>
#include <stdint.h>

// Problem constants
#define DIMK 4096
#define HQ   32
#define HKV  8
#define HD   128
#define REP  (HQ / HKV)
#define SMAX 2048
#define ATT_SCALE 0.08838834764831845f   // 1/sqrt(128)
#define W_SCALE   1024.0f
#define W_UNSCALE 0.0009765625f          // 2^-10

// ---------------------------------------------------------------------------
// Scratch (device globals: allocation-free per harness rules)
// ---------------------------------------------------------------------------
__device__ float g_Q[(size_t)SMAX * HQ * HD];    // fp32 Q before rope/cast
__device__ float g_K[(size_t)SMAX * HKV * HD];   // fp32 K before rope/cast

__device__ __half g_xh[(size_t)SMAX * DIMK];
__device__ __half g_oh[(size_t)SMAX * DIMK];     // attention output (fp16)
__device__ __half g_qh[(size_t)SMAX * HQ * HD];  // fp16 Q after rope
__device__ __half g_kh[(size_t)SMAX * HKV * HD]; // fp16 K after rope
__device__ __half g_vh[(size_t)SMAX * HKV * HD]; // fp16 V
__device__ __half g_wqh[(size_t)4096 * 4096];    // scaled x1024, hi
__device__ __half g_wql[(size_t)4096 * 4096];    // scaled x1024, lo
__device__ __half g_wkh[(size_t)1024 * 4096];
__device__ __half g_wkl[(size_t)1024 * 4096];
__device__ __half g_wvh[(size_t)1024 * 4096];    // plain fp16 (single-pass)
__device__ __half g_woh[(size_t)4096 * 4096];    // plain fp16 (single-pass)

// ---------------------------------------------------------------------------
// Helpers
// ---------------------------------------------------------------------------
static __device__ __forceinline__ uint32_t smem_u32(const void* p) {
    uint32_t a;
    asm("{ .reg .u64 t; cvta.to.shared.u64 t, %1; cvt.u32.u64 %0, t; }"
        : "=r"(a) : "l"(p));
    return a;
}

static __device__ __forceinline__ void ldsm4(uint32_t& r0, uint32_t& r1,
                                             uint32_t& r2, uint32_t& r3,
                                             uint32_t addr) {
    asm volatile("ldmatrix.sync.aligned.m8n8.x4.shared.b16 {%0,%1,%2,%3}, [%4];"
                 : "=r"(r0), "=r"(r1), "=r"(r2), "=r"(r3) : "r"(addr));
}

static __device__ __forceinline__ void ldsm4t(uint32_t& r0, uint32_t& r1,
                                              uint32_t& r2, uint32_t& r3,
                                              uint32_t addr) {
    asm volatile("ldmatrix.sync.aligned.m8n8.x4.trans.shared.b16 {%0,%1,%2,%3}, [%4];"
                 : "=r"(r0), "=r"(r1), "=r"(r2), "=r"(r3) : "r"(addr));
}

static __device__ __forceinline__ void mma16816(float* c, uint32_t a0, uint32_t a1,
                                                uint32_t a2, uint32_t a3,
                                                uint32_t b0, uint32_t b1) {
    asm volatile(
        "mma.sync.aligned.m16n8k16.row.col.f32.f16.f16.f32 "
        "{%0,%1,%2,%3}, {%4,%5,%6,%7}, {%8,%9}, {%0,%1,%2,%3};"
        : "+f"(c[0]), "+f"(c[1]), "+f"(c[2]), "+f"(c[3])
        : "r"(a0), "r"(a1), "r"(a2), "r"(a3), "r"(b0), "r"(b1));
}

static __device__ __forceinline__ uint32_t pack_h2(float a, float b) {
    __half2 h = __floats2half2_rn(a, b);
    return *(uint32_t*)&h;
}

// ---------------------------------------------------------------------------
// Cast fp32 -> fp16.  n % 4 == 0.
// ---------------------------------------------------------------------------
__global__ void cast_kernel(const float* __restrict__ X,
                            __half* __restrict__ H, int n4) {
    int i = blockIdx.x * blockDim.x + threadIdx.x;
    if (i >= n4) return;
    float4 v = ((const float4*)X)[i];
    __half2* Hp = (__half2*)H;
    Hp[2 * i]     = __floats2half2_rn(v.x, v.y);
    Hp[2 * i + 1] = __floats2half2_rn(v.z, v.w);
}

// ---------------------------------------------------------------------------
// Split fp32 weight -> (fp16 hi, fp16 lo), pre-scaled by 1024 (subnormal guard)
// ---------------------------------------------------------------------------
__global__ void split_w_kernel(const float* __restrict__ X,
                               __half* __restrict__ H,
                               __half* __restrict__ L, int n4) {
    int i = blockIdx.x * blockDim.x + threadIdx.x;
    if (i >= n4) return;
    float4 v = ((const float4*)X)[i];
    float sx = v.x * W_SCALE, sy = v.y * W_SCALE;
    float sz = v.z * W_SCALE, sw = v.w * W_SCALE;
    __half hx = __float2half_rn(sx);
    __half hy = __float2half_rn(sy);
    __half hz = __float2half_rn(sz);
    __half hw = __float2half_rn(sw);
    __half lx = __float2half_rn(sx - __half2float(hx));
    __half ly = __float2half_rn(sy - __half2float(hy));
    __half lz = __float2half_rn(sz - __half2float(hz));
    __half lw = __float2half_rn(sw - __half2float(hw));
    __half2* Hp = (__half2*)H;
    __half2* Lp = (__half2*)L;
    Hp[2 * i]     = __half2(hx, hy);
    Hp[2 * i + 1] = __half2(hz, hw);
    Lp[2 * i]     = __half2(lx, ly);
    Lp[2 * i + 1] = __half2(lz, lw);
}

// ---------------------------------------------------------------------------
// RoPE + cast: read fp32 T[S,nh,128], write fp16 rotated.
// ---------------------------------------------------------------------------
__global__ void rope_cast_kernel(const float* __restrict__ T,
                                 const float* __restrict__ fc,
                                 __half* __restrict__ O, int S, int nh) {
    int idx   = blockIdx.x * blockDim.x + threadIdx.x;
    int total = S * nh * (HD / 2);
    if (idx >= total) return;
    int i = idx & 63;
    int h = (idx >> 6) % nh;
    int s = idx / (64 * nh);
    float c  = fc[(size_t)s * HD + 2 * i];
    float sn = fc[(size_t)s * HD + 2 * i + 1];
    size_t base = ((size_t)s * nh + h) * HD + 2 * i;
    float t0 = T[base];
    float t1 = T[base + 1];
    *(__half2*)(O + base) = __floats2half2_rn(t0 * c - t1 * sn, t0 * sn + t1 * c);
}

// ---------------------------------------------------------------------------
// Shared GEMM geometry: 128x128 CTA tile, BK=32, 8 warps (2x4), warp 64x32.
// ---------------------------------------------------------------------------
#define GSTAGES 3
#define GBK     32
#define RS_B    80
#define GTILE_B (128 * RS_B)
#define GSTAGE3_B (3 * GTILE_B)
#define GSMEM3_BYTES (GSTAGES * GSTAGE3_B)
#define GSTAGE2_B (2 * GTILE_B)
#define GSMEM2_BYTES (GSTAGES * GSTAGE2_B)

static __device__ __forceinline__ void tile_cp(uint32_t sbase,
        const __half* __restrict__ src, int r0, int kc, int K, int tid) {
#pragma unroll
    for (int i = 0; i < 2; i++) {
        int ch  = tid + i * 256;
        int r   = ch >> 2;
        int c16 = ch & 3;
        uint32_t dst = sbase + (uint32_t)(r * RS_B + c16 * 16);
        const void* g = src + (size_t)(r0 + r) * K + kc + c16 * 8;
        asm volatile("cp.async.cg.shared.global [%0], [%1], 16;"
                     :: "r"(dst), "l"(g) : "memory");
    }
}

// ---------------------------------------------------------------------------
// 2-pass GEMM: C = (1/1024) * A @ (Bh+Bl)^T
// ---------------------------------------------------------------------------
__global__ __launch_bounds__(256, 2)
void gemm_f16x2(const __half* __restrict__ A, const __half* __restrict__ Bh,
                const __half* __restrict__ Bl,
                float* __restrict__ C, int M, int N, int K) {
    extern __shared__ __align__(16) char smraw[];
    const uint32_t sb  = smem_u32(smraw);
    const int tid  = threadIdx.x;
    const int wid  = tid >> 5;
    const int lane = tid & 31;
    const int wm   = wid >> 2;
    const int wn   = wid & 3;
    const int bm = blockIdx.y * 128;
    const int bn = blockIdx.x * 128;

    const int a_row = wm * 64 + (lane & 15);
    const int a_colB = ((lane >> 4) * 8) * 2;
    const int b_row = wn * 32 + (lane & 7) + ((lane >> 4) * 8);
    const int b_colB = (((lane >> 3) & 1) * 8) * 2;
    const uint32_t a_off = (uint32_t)(a_row * RS_B + a_colB);
    const uint32_t b_off = (uint32_t)(b_row * RS_B + b_colB);

    float acc[4][4][4];
#pragma unroll
    for (int i = 0; i < 4; i++)
#pragma unroll
        for (int j = 0; j < 4; j++)
#pragma unroll
            for (int k = 0; k < 4; k++) acc[i][j][k] = 0.f;

    const int NC = K / GBK;

#pragma unroll
    for (int i = 0; i < GSTAGES; i++) {
        const uint32_t stg = sb + i * GSTAGE3_B;
        tile_cp(stg,               A,  bm, i * GBK, K, tid);
        tile_cp(stg + GTILE_B,     Bh, bn, i * GBK, K, tid);
        tile_cp(stg + 2 * GTILE_B, Bl, bn, i * GBK, K, tid);
        asm volatile("cp.async.commit_group;" ::: "memory");
    }

    int s = 0;
    for (int c = 0; c < NC; c++) {
        asm volatile("cp.async.wait_group %0;" :: "n"(GSTAGES - 1) : "memory");
        __syncthreads();

        const uint32_t stg = sb + s * GSTAGE3_B;
#pragma unroll
        for (int k16 = 0; k16 < 2; k16++) {
            const uint32_t kB = (uint32_t)(k16 * 16 * 2);
            uint32_t a[4][4];
#pragma unroll
            for (int mb = 0; mb < 4; mb++)
                ldsm4(a[mb][0], a[mb][1], a[mb][2], a[mb][3],
                      stg + a_off + mb * (16 * RS_B) + kB);
#pragma unroll
            for (int p = 0; p < 2; p++) {
                const uint32_t Bt = stg + (1 + p) * GTILE_B;
                uint32_t b[8];
                ldsm4(b[0], b[1], b[2], b[3], Bt + b_off + kB);
                ldsm4(b[4], b[5], b[6], b[7], Bt + b_off + 16 * RS_B + kB);
#pragma unroll
                for (int mb = 0; mb < 4; mb++)
#pragma unroll
                    for (int nb = 0; nb < 4; nb++)
                        mma16816(acc[mb][nb], a[mb][0], a[mb][1], a[mb][2], a[mb][3],
                                 b[2 * nb], b[2 * nb + 1]);
            }
        }
        __syncthreads();

        const int cn = c + GSTAGES;
        if (cn < NC) {
            const uint32_t stg2 = sb + s * GSTAGE3_B;
            tile_cp(stg2,               A,  bm, cn * GBK, K, tid);
            tile_cp(stg2 + GTILE_B,     Bh, bn, cn * GBK, K, tid);
            tile_cp(stg2 + 2 * GTILE_B, Bl, bn, cn * GBK, K, tid);
        }
        asm volatile("cp.async.commit_group;" ::: "memory");

        if (++s == GSTAGES) s = 0;
    }

    const int tr = lane >> 2;
    const int tc = (lane & 3) * 2;
#pragma unroll
    for (int mb = 0; mb < 4; mb++) {
        const int row = bm + wm * 64 + mb * 16 + tr;
#pragma unroll
        for (int nb = 0; nb < 4; nb++) {
            const int col = bn + wn * 32 + nb * 8 + tc;
            float* c0 = C + (size_t)row * N + col;
            *(float2*)c0 = make_float2(acc[mb][nb][0] * W_UNSCALE,
                                       acc[mb][nb][1] * W_UNSCALE);
            float* c1 = C + (size_t)(row + 8) * N + col;
            *(float2*)c1 = make_float2(acc[mb][nb][2] * W_UNSCALE,
                                       acc[mb][nb][3] * W_UNSCALE);
        }
    }
}

// ---------------------------------------------------------------------------
// 1-pass GEMM: C = A @ B^T  (templated output type: float or __half)
// ---------------------------------------------------------------------------
template <typename TOut>
__global__ __launch_bounds__(256, 2)
void gemm_f16_t(const __half* __restrict__ A, const __half* __restrict__ B,
                TOut* __restrict__ C, int M, int N, int K) {
    extern __shared__ __align__(16) char smraw[];
    const uint32_t sb  = smem_u32(smraw);
    const int tid  = threadIdx.x;
    const int wid  = tid >> 5;
    const int lane = tid & 31;
    const int wm   = wid >> 2;
    const int wn   = wid & 3;
    const int bm = blockIdx.y * 128;
    const int bn = blockIdx.x * 128;

    const int a_row = wm * 64 + (lane & 15);
    const int a_colB = ((lane >> 4) * 8) * 2;
    const int b_row = wn * 32 + (lane & 7) + ((lane >> 4) * 8);
    const int b_colB = (((lane >> 3) & 1) * 8) * 2;
    const uint32_t a_off = (uint32_t)(a_row * RS_B + a_colB);
    const uint32_t b_off = (uint32_t)(b_row * RS_B + b_colB);

    float acc[4][4][4];
#pragma unroll
    for (int i = 0; i < 4; i++)
#pragma unroll
        for (int j = 0; j < 4; j++)
#pragma unroll
            for (int k = 0; k < 4; k++) acc[i][j][k] = 0.f;

    const int NC = K / GBK;

#pragma unroll
    for (int i = 0; i < GSTAGES; i++) {
        const uint32_t stg = sb + i * GSTAGE2_B;
        tile_cp(stg,           A, bm, i * GBK, K, tid);
        tile_cp(stg + GTILE_B, B, bn, i * GBK, K, tid);
        asm volatile("cp.async.commit_group;" ::: "memory");
    }

    int s = 0;
    for (int c = 0; c < NC; c++) {
        asm volatile("cp.async.wait_group %0;" :: "n"(GSTAGES - 1) : "memory");
        __syncthreads();

        const uint32_t stg = sb + s * GSTAGE2_B;
        const uint32_t Bt  = stg + GTILE_B;
#pragma unroll
        for (int k16 = 0; k16 < 2; k16++) {
            const uint32_t kB = (uint32_t)(k16 * 16 * 2);
            uint32_t a[4][4];
#pragma unroll
            for (int mb = 0; mb < 4; mb++)
                ldsm4(a[mb][0], a[mb][1], a[mb][2], a[mb][3],
                      stg + a_off + mb * (16 * RS_B) + kB);
            uint32_t b[8];
            ldsm4(b[0], b[1], b[2], b[3], Bt + b_off + kB);
            ldsm4(b[4], b[5], b[6], b[7], Bt + b_off + 16 * RS_B + kB);
#pragma unroll
            for (int mb = 0; mb < 4; mb++)
#pragma unroll
                for (int nb = 0; nb < 4; nb++)
                    mma16816(acc[mb][nb], a[mb][0], a[mb][1], a[mb][2], a[mb][3],
                             b[2 * nb], b[2 * nb + 1]);
        }
        __syncthreads();

        const int cn = c + GSTAGES;
        if (cn < NC) {
            const uint32_t stg2 = sb + s * GSTAGE2_B;
            tile_cp(stg2,           A, bm, cn * GBK, K, tid);
            tile_cp(stg2 + GTILE_B, B, bn, cn * GBK, K, tid);
        }
        asm volatile("cp.async.commit_group;" ::: "memory");

        if (++s == GSTAGES) s = 0;
    }

    const int tr = lane >> 2;
    const int tc = (lane & 3) * 2;
#pragma unroll
    for (int mb = 0; mb < 4; mb++) {
        const int row = bm + wm * 64 + mb * 16 + tr;
#pragma unroll
        for (int nb = 0; nb < 4; nb++) {
            const int col = bn + wn * 32 + nb * 8 + tc;
            if (sizeof(TOut) == 4) {
                float* c0 = (float*)C + (size_t)row * N + col;
                *(float2*)c0 = make_float2(acc[mb][nb][0], acc[mb][nb][1]);
                float* c1 = (float*)C + (size_t)(row + 8) * N + col;
                *(float2*)c1 = make_float2(acc[mb][nb][2], acc[mb][nb][3]);
            } else {
                __half* c0 = (__half*)C + (size_t)row * N + col;
                *(__half2*)c0 = __floats2half2_rn(acc[mb][nb][0], acc[mb][nb][1]);
                __half* c1 = (__half*)C + (size_t)(row + 8) * N + col;
                *(__half2*)c1 = __floats2half2_rn(acc[mb][nb][2], acc[mb][nb][3]);
            }
        }
    }
}

// ---------------------------------------------------------------------------
// HMMA flash attention: 64q x 64k tiles, 4 warps, online softmax in regs.
// Q/K/V fp16, O written fp16 at [s][h*128+d].
// ---------------------------------------------------------------------------
#define AKS 136                               // half stride (272 B) per row
#define ATTN_SMEM_BYTES (5 * 64 * AKS * 2 + 256)

static __device__ __forceinline__ void attn_load_kv(
        uint32_t uK, uint32_t uV,
        const __half* __restrict__ Kh, const __half* __restrict__ Vh,
        int k0, int kvh, int tid) {
#pragma unroll
    for (int i = 0; i < 8; i++) {
        int ch = tid + i * 128;
        int r  = ch >> 4;
        int c  = ch & 15;
        size_t goff = (size_t)(k0 + r) * (HKV * HD) + kvh * HD + c * 8;
        uint32_t soff = (uint32_t)(r * AKS + c * 8) * 2;
        asm volatile("cp.async.cg.shared.global [%0], [%1], 16;"
                     :: "r"(uK + soff), "l"((const void*)(Kh + goff)) : "memory");
        asm volatile("cp.async.cg.shared.global [%0], [%1], 16;"
                     :: "r"(uV + soff), "l"((const void*)(Vh + goff)) : "memory");
    }
}

__global__ __launch_bounds__(128, 2)
void attn_hmma(const __half* __restrict__ Qh, const __half* __restrict__ Kh,
               const __half* __restrict__ Vh, const int* __restrict__ seqlens,
               int nseq, __half* __restrict__ Oh, int S) {
    extern __shared__ __align__(16) char smraw[];
    const uint32_t sb  = smem_u32(smraw);
    const uint32_t uQ  = sb;
    const uint32_t uK0 = sb + 1 * (64 * AKS * 2);
    const uint32_t uV0 = sb + 3 * (64 * AKS * 2);
    int* seg_s = (int*)(smraw + 5 * (64 * AKS * 2));

    const int tid  = threadIdx.x;
    const int wid  = tid >> 5;
    const int lane = tid & 31;
    const int h    = blockIdx.y;
    const int kvh  = h / REP;
    const int qb   = gridDim.x - 1 - (int)blockIdx.x;   // heavy blocks first
    const int q0   = qb * 64;

    // segment start of q0 (all threads; rows sorted => min over block)
    int kt_lo;
    {
        int cum = 0, ss = 0;
        for (int i = 0; i < nseq; i++) {
            int nc = cum + seqlens[i];
            if (q0 < nc) { ss = cum; break; }
            cum = nc;
        }
        kt_lo = ss >> 6;
    }

    // Q tile -> smem
#pragma unroll
    for (int i = 0; i < 8; i++) {
        int ch = tid + i * 128;
        int r  = ch >> 4;
        int c  = ch & 15;
        uint32_t dst = uQ + (uint32_t)(r * AKS + c * 8) * 2;
        const void* g = Qh + (size_t)(q0 + r) * (HQ * HD) + h * HD + c * 8;
        asm volatile("cp.async.cg.shared.global [%0], [%1], 16;"
                     :: "r"(dst), "l"(g) : "memory");
    }
    asm volatile("cp.async.commit_group;" ::: "memory");

    attn_load_kv(uK0, uV0, Kh, Vh, kt_lo * 64, kvh, tid);
    asm volatile("cp.async.commit_group;" ::: "memory");

    // per-row segment starts
    if (tid < 64) {
        int qg = q0 + tid;
        int cum = 0, ss = 0;
        for (int i = 0; i < nseq; i++) {
            int nc = cum + seqlens[i];
            if (qg < nc) { ss = cum; break; }
            cum = nc;
        }
        seg_s[tid] = ss;
    }

    asm volatile("cp.async.wait_group 0;" ::: "memory");
    __syncthreads();

    // Q fragments (held in registers for whole mainloop)
    uint32_t qf[8][4];
    {
        const uint32_t a_off =
            (uint32_t)((wid * 16 + (lane & 15)) * AKS + (lane >> 4) * 8) * 2;
#pragma unroll
        for (int kb = 0; kb < 8; kb++)
            ldsm4(qf[kb][0], qf[kb][1], qf[kb][2], qf[kb][3],
                  uQ + a_off + kb * 32);
    }

    const uint32_t bk_off =
        (uint32_t)(((lane & 7) + ((lane >> 4) * 8)) * AKS + ((lane >> 3) & 1) * 8) * 2;
    const uint32_t bv_off =
        (uint32_t)((lane & 15) * AKS + (lane >> 4) * 8) * 2;

    const int tr  = lane >> 2;
    const int r0l = wid * 16 + tr;
    const int r0g = q0 + r0l;
    const int r1g = r0g + 8;
    const int ss0 = seg_s[r0l];
    const int ss1 = seg_s[r0l + 8];

    float oa[16][4];
#pragma unroll
    for (int i = 0; i < 16; i++)
#pragma unroll
        for (int j = 0; j < 4; j++) oa[i][j] = 0.f;
    float m0 = -1e30f, m1 = -1e30f, l0 = 0.f, l1 = 0.f;

    const int nt = qb - kt_lo + 1;
    int buf = 0;
    for (int t = 0; t < nt; t++) {
        const int k0 = (kt_lo + t) * 64;
        if (t + 1 < nt)
            attn_load_kv(uK0 + (buf ^ 1) * (64 * AKS * 2),
                         uV0 + (buf ^ 1) * (64 * AKS * 2),
                         Kh, Vh, (kt_lo + t + 1) * 64, kvh, tid);
        asm volatile("cp.async.commit_group;" ::: "memory");
        if (t > 0) {
            if (t + 1 < nt)
                asm volatile("cp.async.wait_group 1;" ::: "memory");
            else
                asm volatile("cp.async.wait_group 0;" ::: "memory");
            __syncthreads();
        }

        const uint32_t uKb = uK0 + buf * (64 * AKS * 2);
        const uint32_t uVb = uV0 + buf * (64 * AKS * 2);

        // S = Q @ K^T  (warp tile 16x64)
        float sc[8][4];
#pragma unroll
        for (int i = 0; i < 8; i++)
#pragma unroll
            for (int j = 0; j < 4; j++) sc[i][j] = 0.f;
#pragma unroll
        for (int kb = 0; kb < 8; kb++) {
#pragma unroll
            for (int nbp = 0; nbp < 4; nbp++) {
                uint32_t b0, b1, b2, b3;
                ldsm4(b0, b1, b2, b3,
                      uKb + bk_off + nbp * (16 * AKS * 2) + kb * 32);
                mma16816(sc[2 * nbp],     qf[kb][0], qf[kb][1], qf[kb][2], qf[kb][3], b0, b1);
                mma16816(sc[2 * nbp + 1], qf[kb][0], qf[kb][1], qf[kb][2], qf[kb][3], b2, b3);
            }
        }

        // mask + online softmax
        float mx0 = -1e30f, mx1 = -1e30f;
#pragma unroll
        for (int nb = 0; nb < 8; nb++) {
            int kbase = k0 + nb * 8 + (lane & 3) * 2;
#pragma unroll
            for (int c = 0; c < 2; c++) {
                int kg = kbase + c;
                float v0 = sc[nb][c] * ATT_SCALE;
                float v1 = sc[nb][2 + c] * ATT_SCALE;
                v0 = (kg <= r0g && kg >= ss0) ? v0 : -1e30f;
                v1 = (kg <= r1g && kg >= ss1) ? v1 : -1e30f;
                sc[nb][c] = v0; sc[nb][2 + c] = v1;
                mx0 = fmaxf(mx0, v0); mx1 = fmaxf(mx1, v1);
            }
        }
        mx0 = fmaxf(mx0, __shfl_xor_sync(0xffffffffu, mx0, 1));
        mx0 = fmaxf(mx0, __shfl_xor_sync(0xffffffffu, mx0, 2));
        mx1 = fmaxf(mx1, __shfl_xor_sync(0xffffffffu, mx1, 1));
        mx1 = fmaxf(mx1, __shfl_xor_sync(0xffffffffu, mx1, 2));

        const float m0n = fmaxf(m0, mx0);
        const float m1n = fmaxf(m1, mx1);
        const float al0 = __expf(m0 - m0n);
        const float al1 = __expf(m1 - m1n);

        float s0 = 0.f, s1 = 0.f;
#pragma unroll
        for (int nb = 0; nb < 8; nb++) {
#pragma unroll
            for (int c = 0; c < 2; c++) {
                float p0 = __expf(sc[nb][c]     - m0n);
                float p1 = __expf(sc[nb][2 + c] - m1n);
                sc[nb][c] = p0; sc[nb][2 + c] = p1;
                s0 += p0; s1 += p1;
            }
        }
        s0 += __shfl_xor_sync(0xffffffffu, s0, 1);
        s0 += __shfl_xor_sync(0xffffffffu, s0, 2);
        s1 += __shfl_xor_sync(0xffffffffu, s1, 1);
        s1 += __shfl_xor_sync(0xffffffffu, s1, 2);
        l0 = l0 * al0 + s0;
        l1 = l1 * al1 + s1;
        m0 = m0n; m1 = m1n;

#pragma unroll
        for (int nb = 0; nb < 16; nb++) {
            oa[nb][0] *= al0; oa[nb][1] *= al0;
            oa[nb][2] *= al1; oa[nb][3] *= al1;
        }

        // O += P @ V   (P frags via C->A layout identity; V via ldsm.trans)
#pragma unroll
        for (int kb2 = 0; kb2 < 4; kb2++) {
            uint32_t pf0 = pack_h2(sc[2 * kb2][0],     sc[2 * kb2][1]);
            uint32_t pf1 = pack_h2(sc[2 * kb2][2],     sc[2 * kb2][3]);
            uint32_t pf2 = pack_h2(sc[2 * kb2 + 1][0], sc[2 * kb2 + 1][1]);
            uint32_t pf3 = pack_h2(sc[2 * kb2 + 1][2], sc[2 * kb2 + 1][3]);
#pragma unroll
            for (int nbp = 0; nbp < 8; nbp++) {
                uint32_t b0, b1, b2, b3;
                ldsm4t(b0, b1, b2, b3,
                       uVb + bv_off + kb2 * (16 * AKS * 2) + nbp * 32);
                mma16816(oa[2 * nbp],     pf0, pf1, pf2, pf3, b0, b1);
                mma16816(oa[2 * nbp + 1], pf0, pf1, pf2, pf3, b2, b3);
            }
        }

        __syncthreads();   // compute done before next prefetch overwrites
        buf ^= 1;
    }

    // write O (fp16), layout [s][h*128+d]
    const float inv0 = 1.f / l0;
    const float inv1 = 1.f / l1;
    __half* orow0 = Oh + (size_t)r0g * (HQ * HD) + h * HD;
    __half* orow1 = Oh + (size_t)r1g * (HQ * HD) + h * HD;
#pragma unroll
    for (int nb = 0; nb < 16; nb++) {
        int col = nb * 8 + (lane & 3) * 2;
        *(__half2*)(orow0 + col) = __floats2half2_rn(oa[nb][0] * inv0, oa[nb][1] * inv0);
        *(__half2*)(orow1 + col) = __floats2half2_rn(oa[nb][2] * inv1, oa[nb][3] * inv1);
    }
}

// ---------------------------------------------------------------------------
// Launch
// Inputs: 0:x[S,4096] 1:freqs_cis[S,64,2] 2:seqlens[int32 x nseq]
//         3:wq[4096,4096] 4:wk[1024,4096] 5:wv[1024,4096] 6:wo[4096,4096]
// Output: float32 [S, 4096]
// ---------------------------------------------------------------------------
extern "C" void kernel_launch(void* const* d_in, const int* in_sizes, int n_in,
                              void* d_out, int out_size) {
    const float* x  = (const float*)d_in[0];
    const float* fc = (const float*)d_in[1];
    const int*   sl = (const int*)d_in[2];
    const float* wq = (const float*)d_in[3];
    const float* wk = (const float*)d_in[4];
    const float* wv = (const float*)d_in[5];
    const float* wo = (const float*)d_in[6];
    float* out = (float*)d_out;

    const int S    = in_sizes[0] / DIMK;   // 2048
    const int nseq = in_sizes[2];

    float *Qp, *Kp;
    cudaGetSymbolAddress((void**)&Qp, g_Q);
    cudaGetSymbolAddress((void**)&Kp, g_K);

    __half *xh, *oh, *qh, *kh, *vh, *wqh, *wql, *wkh, *wkl, *wvh, *woh;
    cudaGetSymbolAddress((void**)&xh,  g_xh);
    cudaGetSymbolAddress((void**)&oh,  g_oh);
    cudaGetSymbolAddress((void**)&qh,  g_qh);
    cudaGetSymbolAddress((void**)&kh,  g_kh);
    cudaGetSymbolAddress((void**)&vh,  g_vh);
    cudaGetSymbolAddress((void**)&wqh, g_wqh);
    cudaGetSymbolAddress((void**)&wql, g_wql);
    cudaGetSymbolAddress((void**)&wkh, g_wkh);
    cudaGetSymbolAddress((void**)&wkl, g_wkl);
    cudaGetSymbolAddress((void**)&wvh, g_wvh);
    cudaGetSymbolAddress((void**)&woh, g_woh);

    cudaFuncSetAttribute(gemm_f16x2, cudaFuncAttributeMaxDynamicSharedMemorySize,
                         GSMEM3_BYTES);
    cudaFuncSetAttribute(gemm_f16_t<float>, cudaFuncAttributeMaxDynamicSharedMemorySize,
                         GSMEM2_BYTES);
    cudaFuncSetAttribute(gemm_f16_t<__half>, cudaFuncAttributeMaxDynamicSharedMemorySize,
                         GSMEM2_BYTES);
    cudaFuncSetAttribute(attn_hmma, cudaFuncAttributeMaxDynamicSharedMemorySize,
                         ATTN_SMEM_BYTES);

    // Cast activations; split wq/wk (scaled), cast wv/wo (plain fp16)
    {
        int n;
        n = S * DIMK;       cast_kernel<<<(n / 4 + 255) / 256, 256>>>(x, xh, n / 4);
        n = 4096 * 4096;    split_w_kernel<<<(n / 4 + 255) / 256, 256>>>(wq, wqh, wql, n / 4);
        n = 1024 * 4096;    split_w_kernel<<<(n / 4 + 255) / 256, 256>>>(wk, wkh, wkl, n / 4);
        n = 1024 * 4096;    cast_kernel<<<(n / 4 + 255) / 256, 256>>>(wv, wvh, n / 4);
        n = 4096 * 4096;    cast_kernel<<<(n / 4 + 255) / 256, 256>>>(wo, woh, n / 4);
    }

    // QKV projections (Q,K fp32 out for rope; V fp16 out directly)
    gemm_f16x2<<<dim3(4096 / 128, S / 128), 256, GSMEM3_BYTES>>>(xh, wqh, wql, Qp, S, 4096, DIMK);
    gemm_f16x2<<<dim3(1024 / 128, S / 128), 256, GSMEM3_BYTES>>>(xh, wkh, wkl, Kp, S, 1024, DIMK);
    gemm_f16_t<__half><<<dim3(1024 / 128, S / 128), 256, GSMEM2_BYTES>>>(xh, wvh, vh, S, 1024, DIMK);

    // RoPE + cast to fp16
    {
        int tq = S * HQ * (HD / 2);
        rope_cast_kernel<<<(tq + 255) / 256, 256>>>(Qp, fc, qh, S, HQ);
        int tk = S * HKV * (HD / 2);
        rope_cast_kernel<<<(tk + 255) / 256, 256>>>(Kp, fc, kh, S, HKV);
    }

    // Attention (HMMA, fp16 in/out)
    attn_hmma<<<dim3(S / 64, HQ), 128, ATTN_SMEM_BYTES>>>(qh, kh, vh, sl, nseq, oh, S);

    // Output projection (single-pass fp16)
    gemm_f16_t<float><<<dim3(4096 / 128, S / 128), 256, GSMEM2_BYTES>>>(oh, woh, out, S, 4096, DIMK);
}